// round 13
// baseline (speedup 1.0000x reference)
#include <cuda_runtime.h>
#include <cuda_bf16.h>
#include <math.h>
#include <stdint.h>

// B=8, H=W=128, C=128, HEADS=4, d=32, WS=8, SHIFT=4, HIDDEN=512
#define MTOK 131072

// ---------------- scratch (device globals; no allocs allowed) ----------------
static __device__ unsigned short g_wq[384 * 128];
static __device__ unsigned short g_wp[128 * 128];
static __device__ unsigned short g_w1[512 * 128];
static __device__ unsigned short g_w2[128 * 512];

// ---------------- PTX helpers (sm_80+ features only) ----------------
static __device__ __forceinline__ uint32_t smem_u32(const void* p) {
    uint32_t a;
    asm("{ .reg .u64 t; cvta.to.shared.u64 t, %1; cvt.u32.u64 %0, t; }" : "=r"(a) : "l"(p));
    return a;
}
static __device__ __forceinline__ void cpa16(uint32_t s, const void* g) {
    asm volatile("cp.async.cg.shared.global [%0], [%1], 16;" :: "r"(s), "l"(g) : "memory");
}
static __device__ __forceinline__ void ldsm4(uint32_t* r, uint32_t addr) {
    asm volatile("ldmatrix.sync.aligned.m8n8.x4.shared.b16 {%0,%1,%2,%3}, [%4];"
                 : "=r"(r[0]), "=r"(r[1]), "=r"(r[2]), "=r"(r[3]) : "r"(addr));
}
static __device__ __forceinline__ void ldsm4t(uint32_t* r, uint32_t addr) {
    asm volatile("ldmatrix.sync.aligned.m8n8.x4.trans.shared.b16 {%0,%1,%2,%3}, [%4];"
                 : "=r"(r[0]), "=r"(r[1]), "=r"(r[2]), "=r"(r[3]) : "r"(addr));
}
static __device__ __forceinline__ void mma_bf16(float* c,
    uint32_t a0, uint32_t a1, uint32_t a2, uint32_t a3, uint32_t b0, uint32_t b1) {
    asm volatile(
        "mma.sync.aligned.m16n8k16.row.col.f32.bf16.bf16.f32 "
        "{%0,%1,%2,%3}, {%4,%5,%6,%7}, {%8,%9}, {%0,%1,%2,%3};"
        : "+f"(c[0]), "+f"(c[1]), "+f"(c[2]), "+f"(c[3])
        : "r"(a0), "r"(a1), "r"(a2), "r"(a3), "r"(b0), "r"(b1));
}
static __device__ __forceinline__ uint32_t packbf(float a, float b) {
    __nv_bfloat162 p = __floats2bfloat162_rn(a, b);
    return *reinterpret_cast<uint32_t*>(&p);
}

// ---------------- merged fp32 -> bf16 weight conversion ----------------
__global__ __launch_bounds__(256) void f2bf_all(
    const float* __restrict__ s0, unsigned short* __restrict__ d0,
    const float* __restrict__ s1, unsigned short* __restrict__ d1,
    const float* __restrict__ s2, unsigned short* __restrict__ d2,
    const float* __restrict__ s3, unsigned short* __restrict__ d3)
{
    int i = blockIdx.x * 256 + threadIdx.x;
    const float* s; unsigned short* d; int o;
    if (i < 12288)      { s = s0; d = d0; o = i; }
    else if (i < 16384) { s = s1; d = d1; o = i - 12288; }
    else if (i < 32768) { s = s2; d = d2; o = i - 16384; }
    else                { s = s3; d = d3; o = i - 32768; }
    float4 v = ((const float4*)s)[o];
    uint2 u;
    u.x = packbf(v.x, v.y);
    u.y = packbf(v.z, v.w);
    ((uint2*)d)[o] = u;
}

// ------------- 16-warp GEMM core with XOR-addressed ldsm ---------------------
// requires abase/bbase 128B-aligned; addr = (rowbase|(s<<4)) ^ (chunk<<4)
static __device__ __forceinline__ void gemm128(
    uint32_t abase, uint32_t bbase, float acc[2][4][4],
    int wm, int wn, int lrow, int lhi)
{
    uint32_t aB[2], bB[2];
    #pragma unroll
    for (int tm = 0; tm < 2; tm++) {
        int row = wm * 32 + tm * 16 + lrow;
        aB[tm] = abase + (uint32_t)((row << 7) | ((row & 7) << 4));
    }
    #pragma unroll
    for (int t2 = 0; t2 < 2; t2++) {
        int row = wn * 32 + t2 * 16 + lrow;
        bB[t2] = bbase + (uint32_t)((row << 7) | ((row & 7) << 4));
    }
    const uint32_t xl = (uint32_t)lhi << 4;
    #pragma unroll
    for (int kb = 0; kb < 2; kb++) {
        const uint32_t kadd = (uint32_t)kb * 16384u;
        uint32_t aK0 = aB[0] + kadd, aK1 = aB[1] + kadd;
        uint32_t bK0 = bB[0] + kadd, bK1 = bB[1] + kadd;
        #pragma unroll
        for (int ks = 0; ks < 4; ks++) {
            const uint32_t xo = ((uint32_t)ks << 5) | xl;
            uint32_t af[2][4], bf[2][4];
            ldsm4(af[0], aK0 ^ xo);
            ldsm4(af[1], aK1 ^ xo);
            ldsm4(bf[0], bK0 ^ xo);
            ldsm4(bf[1], bK1 ^ xo);
            #pragma unroll
            for (int tm = 0; tm < 2; tm++)
                #pragma unroll
                for (int tn = 0; tn < 4; tn++)
                    mma_bf16(acc[tm][tn],
                             af[tm][0], af[tm][1], af[tm][2], af[tm][3],
                             bf[tn >> 1][tn & 1], bf[tn >> 1][2 + (tn & 1)]);
        }
    }
}

// stage a 128x128 bf16 row-major matrix into 2 swizzled kblocks (512 threads)
static __device__ __forceinline__ void stage128(
    uint32_t dst, const __nv_bfloat16* src, int tid)
{
    #pragma unroll
    for (int it = 0; it < 4; it++) {
        int idx = tid + (it << 9);
        int r = idx >> 4, q = idx & 15;
        int kblk = q >> 3, qi = q & 7;
        uint32_t off = (uint32_t)((r << 7) | (qi << 4));
        off ^= (off >> 3) & 0x70;
        cpa16(dst + (uint32_t)kblk * 16384u + off, src + (size_t)r * 128 + q * 8);
    }
}

// stage MLP weight chunk c: W1 rows [c*128, ...) and W2 cols [c*128, ...)
static __device__ __forceinline__ void mlp_stage_w(
    uint32_t wbuf, const __nv_bfloat16* W1, const __nv_bfloat16* W2, int c, int tid)
{
    const int nc0 = c * 128;
    #pragma unroll
    for (int it = 0; it < 4; it++) {
        int idx = tid + (it << 9);
        int r = idx >> 4, q = idx & 15;
        int kblk = q >> 3, qi = q & 7;
        uint32_t off = (uint32_t)((r << 7) | (qi << 4));
        off ^= (off >> 3) & 0x70;
        cpa16(wbuf + (uint32_t)kblk * 16384u + off,            W1 + (size_t)(nc0 + r) * 128 + q * 8);
        cpa16(wbuf + 32768u + (uint32_t)kblk * 16384u + off,   W2 + (size_t)r * 512 + nc0 + q * 8);
    }
    asm volatile("cp.async.commit_group;" ::: "memory");
}

// in-kernel LayerNorm of one 128-row tile into swizzled A smem (16 warps)
static __device__ __forceinline__ void ln_tile(
    uint32_t A_B, const float* __restrict__ xin,
    const float* __restrict__ gam, const float* __restrict__ bet,
    int m0, int wid, int lane)
{
    float4 g4 = *(const float4*)(gam + lane * 4);
    float4 b4 = *(const float4*)(bet + lane * 4);
    const uint32_t kblk = (lane >= 16) ? 16384u : 0u;
    uint32_t boff0 = (uint32_t)((lane * 4 & 63) * 2);
    #pragma unroll 4
    for (int it = 0; it < 8; it++) {
        const int row = it * 16 + wid;
        const int t = m0 + row;
        int w = t >> 6, n = t & 63;
        int b = w >> 8, wrem = w & 255;
        int wi = wrem >> 4, wj = wrem & 15;
        int y  = (wi * 8 + (n >> 3) + 4) & 127;
        int xc = (wj * 8 + (n & 7) + 4) & 127;
        size_t src = ((size_t)b << 14) + (size_t)y * 128 + xc;
        float4 v = *(const float4*)(xin + src * 128 + lane * 4);
        float s  = v.x + v.y + v.z + v.w;
        float sq = v.x * v.x + v.y * v.y + v.z * v.z + v.w * v.w;
        #pragma unroll
        for (int o = 16; o; o >>= 1) {
            s  += __shfl_xor_sync(0xffffffffu, s,  o);
            sq += __shfl_xor_sync(0xffffffffu, sq, o);
        }
        float mean = s * (1.f / 128.f);
        float rstd = rsqrtf(sq * (1.f / 128.f) - mean * mean + 1e-5f);
        uint32_t u0 = packbf((v.x - mean) * rstd * g4.x + b4.x,
                             (v.y - mean) * rstd * g4.y + b4.y);
        uint32_t u1 = packbf((v.z - mean) * rstd * g4.z + b4.z,
                             (v.w - mean) * rstd * g4.w + b4.w);
        uint32_t boff = (uint32_t)(row << 7) + boff0;
        boff ^= (boff >> 3) & 0x70;
        asm volatile("st.shared.v2.b32 [%0], {%1, %2};"
                     :: "r"(A_B + kblk + boff), "r"(u0), "r"(u1) : "memory");
    }
}

// ---------------- mega kernel: full Swin block per 128-token CTA --------------
#define FSMEM 225424
__device__ __forceinline__ int reg3(int y) { return y < 120 ? 0 : (y < 124 ? 1 : 2); }

__global__ __launch_bounds__(512) void swin_fused(
    const float* __restrict__ x, const float* __restrict__ n1g,
    const float* __restrict__ n1b, const unsigned short* __restrict__ wqu,
    const float* __restrict__ qkv_b, const unsigned short* __restrict__ wpu,
    const float* __restrict__ proj_b, const float* __restrict__ rpb,
    const float* __restrict__ n2g, const float* __restrict__ n2b,
    const unsigned short* __restrict__ w1u, const float* __restrict__ b1,
    const unsigned short* __restrict__ w2u, const float* __restrict__ b2,
    float* __restrict__ out)
{
    extern __shared__ char dsm[];
    const __nv_bfloat16* wq = (const __nv_bfloat16*)wqu;
    const __nv_bfloat16* wp = (const __nv_bfloat16*)wpu;
    const __nv_bfloat16* W1 = (const __nv_bfloat16*)w1u;
    const __nv_bfloat16* W2 = (const __nv_bfloat16*)w2u;
    const uint32_t sraw = smem_u32(dsm);
    const uint32_t s0 = (sraw + 127u) & ~127u;       // 128B-aligned for XOR ldsm
    const uint32_t A_B = s0;
    const uint32_t Q_B = s0 + 32768u;
    const uint32_t W_B = s0 + 155648u;
    const uint32_t HID = s0 + 32768u;
    const uint32_t AUX = s0 + 221184u;
    float* rpbs = (float*)(size_t)0;  // placeholder; use smem addrs directly
    // AUX layout: rpb floats at AUX, rgt ints at AUX+3600
    const int tid = threadIdx.x, lane = tid & 31, wid = tid >> 5;
    const int wm = wid >> 2, wn = wid & 3;
    const int m0 = blockIdx.x * 128;
    const int lrow = (lane & 7) + ((lane >> 3) & 1) * 8;
    const int lhi  = lane >> 4;

    // C-pointer views of AUX (via generic pointer arithmetic on dsm)
    float* rpbf = (float*)(dsm + (AUX - sraw));
    int*   rgt  = (int*)(dsm + (AUX - sraw) + 3600);
    float* red  = rpbf;   // reused after attention

    stage128(W_B, wq, tid);
    asm volatile("cp.async.commit_group;" ::: "memory");

    ln_tile(A_B, x, n1g, n1b, m0, wid, lane);

    for (int i = tid; i < 900; i += 512) rpbf[i] = rpb[i];
    if (tid < 128) {
        int lw = tid >> 6, n = tid & 63;
        int w = (m0 >> 6) + lw, wrem = w & 255;
        int wi = wrem >> 4, wj = wrem & 15;
        rgt[tid] = 3 * reg3(wi * 8 + (n >> 3)) + reg3(wj * 8 + (n & 7));
    }

    // ---- phase 1: QKV GEMM, 3 chunks of N=128 ----
    for (int c = 0; c < 3; c++) {
        if (c < 2) {
            stage128(W_B + (uint32_t)((c + 1) & 1) * 32768u, wq + (size_t)(c + 1) * 128 * 128, tid);
            asm volatile("cp.async.commit_group;" ::: "memory");
            asm volatile("cp.async.wait_group 1;" ::: "memory");
        } else {
            asm volatile("cp.async.wait_group 0;" ::: "memory");
        }
        __syncthreads();

        float acc[2][4][4];
        #pragma unroll
        for (int a = 0; a < 2; a++)
            #pragma unroll
            for (int b = 0; b < 4; b++)
                #pragma unroll
                for (int q = 0; q < 4; q++) acc[a][b][q] = 0.f;
        gemm128(A_B, W_B + (uint32_t)(c & 1) * 32768u, acc, wm, wn, lrow, lhi);

        float2 bs[4];
        #pragma unroll
        for (int tn = 0; tn < 4; tn++)
            bs[tn] = *(const float2*)(qkv_b + c * 128 + wn * 32 + tn * 8 + (lane & 3) * 2);
        const uint32_t slice = Q_B + (uint32_t)(c * 4 + wn) * 10240u;
        #pragma unroll
        for (int tm = 0; tm < 2; tm++) {
            #pragma unroll
            for (int h8 = 0; h8 < 2; h8++) {
                const int row = wm * 32 + tm * 16 + (lane >> 2) + h8 * 8;
                #pragma unroll
                for (int tn = 0; tn < 4; tn++) {
                    const int c32 = tn * 8 + (lane & 3) * 2;
                    float v0 = acc[tm][tn][h8 * 2 + 0] + bs[tn].x;
                    float v1 = acc[tm][tn][h8 * 2 + 1] + bs[tn].y;
                    asm volatile("st.shared.b32 [%0], %1;"
                                 :: "r"(slice + (uint32_t)(row * 80 + c32 * 2)),
                                    "r"(packbf(v0, v1)) : "memory");
                }
            }
        }
        __syncthreads();
    }

    // prefetch proj weights (group P)
    stage128(W_B + 32768u, wp, tid);
    asm volatile("cp.async.commit_group;" ::: "memory");

    // ---- phase 2: attention (16 warps: window, head-pair, row-quarter) ----
    {
        const int lw  = wid >> 3;
        const int hp  = (wid >> 2) & 1;
        const int wm4 = wid & 3;
        const uint32_t lh16 = (uint32_t)lhi * 16u;
        const uint32_t rowbase = (uint32_t)(lw * 64) * 80u;
        const int r0 = wm4 * 16 + (lane >> 2), r1 = r0 + 8;
        const int rg0 = rgt[lw * 64 + r0], rg1 = rgt[lw * 64 + r1];
        const int i1a = r0 >> 3, j1a = r0 & 7, i1b = r1 >> 3, j1b = r1 & 7;
        const int c0 = (lane & 3) * 2;
        const float scale = 0.17677669529663689f;

        const int wthis = (m0 >> 6) + lw;
        const int wtr = wthis & 255;
        const bool edge = ((wtr >> 4) == 15) || ((wtr & 15) == 15);

        const float* pb0 = rpbf + (size_t)((i1a * 15 + j1a + 112 - c0) * 4);
        const float* pb1 = rpbf + (size_t)((i1b * 15 + j1b + 112 - c0) * 4);

        // hoisted ldsm row offsets
        const uint32_t qoff = (uint32_t)((wm4 * 16 + lrow) * 80) + lh16 + rowbase;
        const uint32_t koff = (uint32_t)(lrow * 80) + lh16 + rowbase;

        #pragma unroll 1
        for (int hh = 0; hh < 2; hh++) {
            const int h = hp * 2 + hh;
            const uint32_t qsl = Q_B + (uint32_t)(0 + h) * 10240u;
            const uint32_t ksl = Q_B + (uint32_t)(4 + h) * 10240u;
            const uint32_t vsl = Q_B + (uint32_t)(8 + h) * 10240u;
            const float* pbh0 = pb0 + h;
            const float* pbh1 = pb1 + h;

            uint32_t qa[2][4];
            {
                uint32_t addr = qsl + qoff;
                ldsm4(qa[0], addr);
                ldsm4(qa[1], addr + 32);
            }
            uint32_t kf[4][2][4];
            #pragma unroll
            for (int nt = 0; nt < 4; nt++) {
                uint32_t addr = ksl + koff + (uint32_t)(nt * 1280);
                ldsm4(kf[nt][0], addr);
                ldsm4(kf[nt][1], addr + 32);
            }

            float sc[8][4];
            #pragma unroll
            for (int i = 0; i < 8; i++)
                #pragma unroll
                for (int q = 0; q < 4; q++) sc[i][q] = 0.f;
            #pragma unroll
            for (int nt8 = 0; nt8 < 8; nt8++) {
                const int nt = nt8 >> 1, ii = nt8 & 1;
                mma_bf16(sc[nt8], qa[0][0], qa[0][1], qa[0][2], qa[0][3],
                         kf[nt][0][ii], kf[nt][0][2 + ii]);
                mma_bf16(sc[nt8], qa[1][0], qa[1][1], qa[1][2], qa[1][3],
                         kf[nt][1][ii], kf[nt][1][2 + ii]);
            }

            if (!edge) {
                #pragma unroll
                for (int nt8 = 0; nt8 < 8; nt8++) {
                    sc[nt8][0] = fmaf(sc[nt8][0], scale, pbh0[-nt8 * 60]);
                    sc[nt8][1] = fmaf(sc[nt8][1], scale, pbh0[-nt8 * 60 - 4]);
                    sc[nt8][2] = fmaf(sc[nt8][2], scale, pbh1[-nt8 * 60]);
                    sc[nt8][3] = fmaf(sc[nt8][3], scale, pbh1[-nt8 * 60 - 4]);
                }
            } else {
                const int* rg = rgt + lw * 64;
                #pragma unroll
                for (int nt8 = 0; nt8 < 8; nt8++) {
                    const int colb = nt8 * 8 + c0;
                    int rga = rg[colb], rgb = rg[colb + 1];
                    float v0 = fmaf(sc[nt8][0], scale, pbh0[-nt8 * 60]);
                    float v1 = fmaf(sc[nt8][1], scale, pbh0[-nt8 * 60 - 4]);
                    float v2 = fmaf(sc[nt8][2], scale, pbh1[-nt8 * 60]);
                    float v3 = fmaf(sc[nt8][3], scale, pbh1[-nt8 * 60 - 4]);
                    if (rga != rg0) v0 -= 100.f;
                    if (rgb != rg0) v1 -= 100.f;
                    if (rga != rg1) v2 -= 100.f;
                    if (rgb != rg1) v3 -= 100.f;
                    sc[nt8][0] = v0; sc[nt8][1] = v1; sc[nt8][2] = v2; sc[nt8][3] = v3;
                }
            }

            float mx0 = -1e30f, mx1 = -1e30f;
            #pragma unroll
            for (int nt8 = 0; nt8 < 8; nt8++) {
                mx0 = fmaxf(mx0, fmaxf(sc[nt8][0], sc[nt8][1]));
                mx1 = fmaxf(mx1, fmaxf(sc[nt8][2], sc[nt8][3]));
            }
            #pragma unroll
            for (int o = 1; o <= 2; o <<= 1) {
                mx0 = fmaxf(mx0, __shfl_xor_sync(0xffffffffu, mx0, o));
                mx1 = fmaxf(mx1, __shfl_xor_sync(0xffffffffu, mx1, o));
            }
            float sm0 = 0.f, sm1 = 0.f;
            #pragma unroll
            for (int nt8 = 0; nt8 < 8; nt8++) {
                sc[nt8][0] = __expf(sc[nt8][0] - mx0);
                sc[nt8][1] = __expf(sc[nt8][1] - mx0);
                sc[nt8][2] = __expf(sc[nt8][2] - mx1);
                sc[nt8][3] = __expf(sc[nt8][3] - mx1);
                sm0 += sc[nt8][0] + sc[nt8][1];
                sm1 += sc[nt8][2] + sc[nt8][3];
            }
            #pragma unroll
            for (int o = 1; o <= 2; o <<= 1) {
                sm0 += __shfl_xor_sync(0xffffffffu, sm0, o);
                sm1 += __shfl_xor_sync(0xffffffffu, sm1, o);
            }
            const float inv0 = 1.f / sm0, inv1 = 1.f / sm1;

            float oc[4][4];
            #pragma unroll
            for (int nt = 0; nt < 4; nt++)
                #pragma unroll
                for (int q = 0; q < 4; q++) oc[nt][q] = 0.f;
            #pragma unroll
            for (int kc = 0; kc < 4; kc++) {
                const uint32_t a0 = packbf(sc[2 * kc][0],     sc[2 * kc][1]);
                const uint32_t a1 = packbf(sc[2 * kc][2],     sc[2 * kc][3]);
                const uint32_t a2 = packbf(sc[2 * kc + 1][0], sc[2 * kc + 1][1]);
                const uint32_t a3 = packbf(sc[2 * kc + 1][2], sc[2 * kc + 1][3]);
                uint32_t vf0[4], vf1[4];
                const uint32_t vaddr = vsl + koff + (uint32_t)(kc * 1280);
                ldsm4t(vf0, vaddr);
                ldsm4t(vf1, vaddr + 32);
                mma_bf16(oc[0], a0, a1, a2, a3, vf0[0], vf0[1]);
                mma_bf16(oc[1], a0, a1, a2, a3, vf0[2], vf0[3]);
                mma_bf16(oc[2], a0, a1, a2, a3, vf1[0], vf1[1]);
                mma_bf16(oc[3], a0, a1, a2, a3, vf1[2], vf1[3]);
            }

            #pragma unroll
            for (int nt = 0; nt < 4; nt++) {
                const int ch = h * 32 + nt * 8 + c0;
                const uint32_t kblk = (uint32_t)(ch >> 6) * 16384u;
                uint32_t b0 = (uint32_t)(((lw * 64 + r0) << 7) + ((ch & 63) << 1));
                uint32_t b1 = (uint32_t)(((lw * 64 + r1) << 7) + ((ch & 63) << 1));
                b0 ^= (b0 >> 3) & 0x70;
                b1 ^= (b1 >> 3) & 0x70;
                asm volatile("st.shared.b32 [%0], %1;" ::
                    "r"(A_B + kblk + b0), "r"(packbf(oc[nt][0] * inv0, oc[nt][1] * inv0)) : "memory");
                asm volatile("st.shared.b32 [%0], %1;" ::
                    "r"(A_B + kblk + b1), "r"(packbf(oc[nt][2] * inv1, oc[nt][3] * inv1)) : "memory");
            }
        }
    }
    __syncthreads();   // attn outputs in A_B; Q_B now dead

    // prefetch MLP weight chunk 0 into pool (Q_B region; group M0)
    mlp_stage_w(Q_B + 32768u, W1, W2, 0, tid);
    asm volatile("cp.async.wait_group 1;" ::: "memory");  // proj weights (P) ready
    __syncthreads();

    // ---- phase 3: proj GEMM; x1 kept in registers ----
    float xv[2][4][4];
    {
        #pragma unroll
        for (int a = 0; a < 2; a++)
            #pragma unroll
            for (int b = 0; b < 4; b++)
                #pragma unroll
                for (int q = 0; q < 4; q++) xv[a][b][q] = 0.f;
        gemm128(A_B, W_B + 32768u, xv, wm, wn, lrow, lhi);

        float2 bs[4];
        #pragma unroll
        for (int tn = 0; tn < 4; tn++)
            bs[tn] = *(const float2*)(proj_b + wn * 32 + tn * 8 + (lane & 3) * 2);
        #pragma unroll
        for (int tm = 0; tm < 2; tm++) {
            #pragma unroll
            for (int h8 = 0; h8 < 2; h8++) {
                const int m = m0 + wm * 32 + tm * 16 + (lane >> 2) + h8 * 8;
                int w = m >> 6, nt2 = m & 63;
                int b = w >> 8, wrem = w & 255;
                int wwi = wrem >> 4, wwj = wrem & 15;
                int yf = (wwi * 8 + (nt2 >> 3) + 4) & 127;
                int xf = (wwj * 8 + (nt2 & 7) + 4) & 127;
                size_t mo = ((size_t)b << 14) + (size_t)yf * 128 + xf;
                float s = 0.f, sq = 0.f;
                #pragma unroll
                for (int tn = 0; tn < 4; tn++) {
                    const int nn = wn * 32 + tn * 8 + (lane & 3) * 2;
                    float2 r2 = *(const float2*)(x + mo * 128 + nn);
                    float v0 = xv[tm][tn][h8 * 2 + 0] + bs[tn].x + r2.x;
                    float v1 = xv[tm][tn][h8 * 2 + 1] + bs[tn].y + r2.y;
                    xv[tm][tn][h8 * 2 + 0] = v0;
                    xv[tm][tn][h8 * 2 + 1] = v1;
                    s += v0 + v1;
                    sq += v0 * v0 + v1 * v1;
                }
                #pragma unroll
                for (int o = 1; o <= 2; o <<= 1) {
                    s  += __shfl_xor_sync(0xffffffffu, s,  o);
                    sq += __shfl_xor_sync(0xffffffffu, sq, o);
                }
                if ((lane & 3) == 0) {
                    const int rloc = wm * 32 + tm * 16 + (lane >> 2) + h8 * 8;
                    red[rloc * 8 + wn * 2 + 0] = s;
                    red[rloc * 8 + wn * 2 + 1] = sq;
                }
            }
        }
    }
    __syncthreads();

    // ---- phase 4: LN2 from registers -> A_B (bf16 swizzled) ----
    #pragma unroll
    for (int tm = 0; tm < 2; tm++) {
        #pragma unroll
        for (int h8 = 0; h8 < 2; h8++) {
            const int rloc = wm * 32 + tm * 16 + (lane >> 2) + h8 * 8;
            float4 p0 = *(const float4*)(red + rloc * 8);
            float4 p1 = *(const float4*)(red + rloc * 8 + 4);
            float s  = p0.x + p0.z + p1.x + p1.z;
            float sq = p0.y + p0.w + p1.y + p1.w;
            float mean = s * (1.f / 128.f);
            float rstd = rsqrtf(sq * (1.f / 128.f) - mean * mean + 1e-5f);
            #pragma unroll
            for (int tn = 0; tn < 4; tn++) {
                const int nn = wn * 32 + tn * 8 + (lane & 3) * 2;
                float2 gg = *(const float2*)(n2g + nn);
                float2 bb = *(const float2*)(n2b + nn);
                float v0 = (xv[tm][tn][h8 * 2 + 0] - mean) * rstd * gg.x + bb.x;
                float v1 = (xv[tm][tn][h8 * 2 + 1] - mean) * rstd * gg.y + bb.y;
                const uint32_t kblk = (uint32_t)(nn >> 6) * 16384u;
                uint32_t boff = (uint32_t)((rloc << 7) + ((nn & 63) << 1));
                boff ^= (boff >> 3) & 0x70;
                asm volatile("st.shared.b32 [%0], %1;"
                             :: "r"(A_B + kblk + boff), "r"(packbf(v0, v1)) : "memory");
            }
        }
    }
    __syncthreads();

    // ---- phase 5: MLP loop (hid @ HID, weights double-buffered in pool) ----
    float acc2[2][4][4];
    #pragma unroll
    for (int a = 0; a < 2; a++)
        #pragma unroll
        for (int b = 0; b < 4; b++)
            #pragma unroll
            for (int q = 0; q < 4; q++) acc2[a][b][q] = 0.f;

    for (int c = 0; c < 4; c++) {
        if (c + 1 < 4) {
            mlp_stage_w(Q_B + 32768u + (uint32_t)((c + 1) & 1) * 65536u, W1, W2, c + 1, tid);
            asm volatile("cp.async.wait_group 1;" ::: "memory");
        } else {
            asm volatile("cp.async.wait_group 0;" ::: "memory");
        }
        __syncthreads();

        const uint32_t wb = Q_B + 32768u + (uint32_t)(c & 1) * 65536u;

        float acc1[2][4][4];
        #pragma unroll
        for (int a = 0; a < 2; a++)
            #pragma unroll
            for (int b = 0; b < 4; b++)
                #pragma unroll
                for (int q = 0; q < 4; q++) acc1[a][b][q] = 0.f;
        gemm128(A_B, wb, acc1, wm, wn, lrow, lhi);

        {
            float2 bs1[4];
            #pragma unroll
            for (int tn = 0; tn < 4; tn++)
                bs1[tn] = *(const float2*)(b1 + c * 128 + wn * 32 + tn * 8 + (lane & 3) * 2);
            #pragma unroll
            for (int tm = 0; tm < 2; tm++) {
                #pragma unroll
                for (int h = 0; h < 2; h++) {
                    const int row = wm * 32 + tm * 16 + (lane >> 2) + h * 8;
                    #pragma unroll
                    for (int tn = 0; tn < 4; tn++) {
                        const int nn = wn * 32 + tn * 8 + (lane & 3) * 2;
                        float v0 = acc1[tm][tn][h * 2 + 0] + bs1[tn].x;
                        float v1 = acc1[tm][tn][h * 2 + 1] + bs1[tn].y;
                        v0 = 0.5f * v0 * (1.f + erff(v0 * 0.70710678118654752f));
                        v1 = 0.5f * v1 * (1.f + erff(v1 * 0.70710678118654752f));
                        uint32_t boff = (uint32_t)((row << 7) + (nn & 63) * 2);
                        boff ^= (boff >> 3) & 0x70;
                        uint32_t dst = HID + ((nn >= 64) ? 16384u : 0u) + boff;
                        asm volatile("st.shared.b32 [%0], %1;" :: "r"(dst), "r"(packbf(v0, v1)) : "memory");
                    }
                }
            }
        }
        __syncthreads();

        gemm128(HID, wb + 32768u, acc2, wm, wn, lrow, lhi);
        __syncthreads();
    }

    // ---- epilogue: out = acc2 + b2 + x1(regs), scattered ----
    float2 bs[4];
    #pragma unroll
    for (int tn = 0; tn < 4; tn++)
        bs[tn] = *(const float2*)(b2 + wn * 32 + tn * 8 + (lane & 3) * 2);
    #pragma unroll
    for (int tm = 0; tm < 2; tm++) {
        #pragma unroll
        for (int h8 = 0; h8 < 2; h8++) {
            const int m = m0 + wm * 32 + tm * 16 + (lane >> 2) + h8 * 8;
            int w = m >> 6, nt2 = m & 63;
            int b = w >> 8, wrem = w & 255;
            int wwi = wrem >> 4, wwj = wrem & 15;
            int yf = (wwi * 8 + (nt2 >> 3) + 4) & 127;
            int xf = (wwj * 8 + (nt2 & 7) + 4) & 127;
            size_t mo = ((size_t)b << 14) + (size_t)yf * 128 + xf;
            #pragma unroll
            for (int tn = 0; tn < 4; tn++) {
                const int nn = wn * 32 + tn * 8 + (lane & 3) * 2;
                float v0 = acc2[tm][tn][h8 * 2 + 0] + bs[tn].x + xv[tm][tn][h8 * 2 + 0];
                float v1 = acc2[tm][tn][h8 * 2 + 1] + bs[tn].y + xv[tm][tn][h8 * 2 + 1];
                *(float2*)(out + mo * 128 + nn) = make_float2(v0, v1);
            }
        }
    }
}

// ---------------- launch ----------------
extern "C" void kernel_launch(void* const* d_in, const int* in_sizes, int n_in,
                              void* d_out, int out_size)
{
    const float* x      = (const float*)d_in[0];
    const float* rpb    = (const float*)d_in[1];
    const float* n1g    = (const float*)d_in[2];
    const float* n1b    = (const float*)d_in[3];
    const float* qkv_w  = (const float*)d_in[4];
    const float* qkv_b  = (const float*)d_in[5];
    const float* proj_w = (const float*)d_in[6];
    const float* proj_b = (const float*)d_in[7];
    const float* n2g    = (const float*)d_in[8];
    const float* n2b    = (const float*)d_in[9];
    const float* fc1_w  = (const float*)d_in[10];
    const float* fc1_b  = (const float*)d_in[11];
    const float* fc2_w  = (const float*)d_in[12];
    const float* fc2_b  = (const float*)d_in[13];
    float* out = (float*)d_out;

    unsigned short *wq, *wp, *w1, *w2;
    cudaGetSymbolAddress((void**)&wq,  g_wq);
    cudaGetSymbolAddress((void**)&wp,  g_wp);
    cudaGetSymbolAddress((void**)&w1,  g_w1);
    cudaGetSymbolAddress((void**)&w2,  g_w2);

    cudaFuncSetAttribute(swin_fused, cudaFuncAttributeMaxDynamicSharedMemorySize, FSMEM);

    f2bf_all<<<192, 256>>>(qkv_w, wq, proj_w, wp, fc1_w, w1, fc2_w, w2);

    swin_fused<<<MTOK / 128, 512, FSMEM>>>(x, n1g, n1b, wq, qkv_b, wp, proj_b, rpb,
                                           n2g, n2b, w1, fc1_b, w2, fc2_b, out);
}

// round 14
// speedup vs baseline: 1.1760x; 1.1760x over previous
#include <cuda_runtime.h>
#include <cuda_bf16.h>
#include <math.h>
#include <stdint.h>

// B=8, H=W=128, C=128, HEADS=4, d=32, WS=8, SHIFT=4, HIDDEN=512
#define MTOK 131072

// ---------------- scratch (device globals; no allocs allowed) ----------------
static __device__ unsigned short g_wq[384 * 128];
static __device__ unsigned short g_wp[128 * 128];
static __device__ unsigned short g_w1[512 * 128];
static __device__ unsigned short g_w2[128 * 512];

// ---------------- PTX helpers (sm_80+ features only) ----------------
static __device__ __forceinline__ uint32_t smem_u32(const void* p) {
    uint32_t a;
    asm("{ .reg .u64 t; cvta.to.shared.u64 t, %1; cvt.u32.u64 %0, t; }" : "=r"(a) : "l"(p));
    return a;
}
static __device__ __forceinline__ void cpa16(uint32_t s, const void* g) {
    asm volatile("cp.async.cg.shared.global [%0], [%1], 16;" :: "r"(s), "l"(g) : "memory");
}
static __device__ __forceinline__ void ldsm4(uint32_t* r, uint32_t addr) {
    asm volatile("ldmatrix.sync.aligned.m8n8.x4.shared.b16 {%0,%1,%2,%3}, [%4];"
                 : "=r"(r[0]), "=r"(r[1]), "=r"(r[2]), "=r"(r[3]) : "r"(addr));
}
static __device__ __forceinline__ void ldsm4t(uint32_t* r, uint32_t addr) {
    asm volatile("ldmatrix.sync.aligned.m8n8.x4.trans.shared.b16 {%0,%1,%2,%3}, [%4];"
                 : "=r"(r[0]), "=r"(r[1]), "=r"(r[2]), "=r"(r[3]) : "r"(addr));
}
static __device__ __forceinline__ void mma_bf16(float* c,
    uint32_t a0, uint32_t a1, uint32_t a2, uint32_t a3, uint32_t b0, uint32_t b1) {
    asm volatile(
        "mma.sync.aligned.m16n8k16.row.col.f32.bf16.bf16.f32 "
        "{%0,%1,%2,%3}, {%4,%5,%6,%7}, {%8,%9}, {%0,%1,%2,%3};"
        : "+f"(c[0]), "+f"(c[1]), "+f"(c[2]), "+f"(c[3])
        : "r"(a0), "r"(a1), "r"(a2), "r"(a3), "r"(b0), "r"(b1));
}
static __device__ __forceinline__ uint32_t packbf(float a, float b) {
    __nv_bfloat162 p = __floats2bfloat162_rn(a, b);
    return *reinterpret_cast<uint32_t*>(&p);
}
// tanh-form GELU via sigmoid: x * sigma(2*0.79788456*(x + 0.044715 x^3))
static __device__ __forceinline__ float gelu_fast(float v) {
    float a = 1.5957691216057308f * fmaf(0.044715f * v, v * v, v);
    return __fdividef(v, 1.f + __expf(-a));
}

// ---------------- merged fp32 -> bf16 weight conversion ----------------
__global__ __launch_bounds__(256) void f2bf_all(
    const float* __restrict__ s0, unsigned short* __restrict__ d0,
    const float* __restrict__ s1, unsigned short* __restrict__ d1,
    const float* __restrict__ s2, unsigned short* __restrict__ d2,
    const float* __restrict__ s3, unsigned short* __restrict__ d3)
{
    int i = blockIdx.x * 256 + threadIdx.x;
    const float* s; unsigned short* d; int o;
    if (i < 12288)      { s = s0; d = d0; o = i; }
    else if (i < 16384) { s = s1; d = d1; o = i - 12288; }
    else if (i < 32768) { s = s2; d = d2; o = i - 16384; }
    else                { s = s3; d = d3; o = i - 32768; }
    float4 v = ((const float4*)s)[o];
    uint2 u;
    u.x = packbf(v.x, v.y);
    u.y = packbf(v.z, v.w);
    ((uint2*)d)[o] = u;
}

// ------------- 16-warp GEMM core: C128x128 += A(2 kblk) @ B(2 kblk)^T ---------
static __device__ __forceinline__ void gemm128(
    uint32_t abase, uint32_t bbase, float acc[2][4][4],
    int wm, int wn, int lrow, int lhi)
{
    #pragma unroll
    for (int kb = 0; kb < 2; kb++) {
        const uint32_t ab = abase + (uint32_t)kb * 16384u;
        const uint32_t bb = bbase + (uint32_t)kb * 16384u;
        #pragma unroll
        for (int ks = 0; ks < 4; ks++) {
            uint32_t af[2][4], bf[2][4];
            const int chunk = ks * 2 + lhi;
            #pragma unroll
            for (int tm = 0; tm < 2; tm++) {
                int row = wm * 32 + tm * 16 + lrow;
                ldsm4(af[tm], ab + (uint32_t)(row * 128 + ((chunk ^ (row & 7)) << 4)));
            }
            #pragma unroll
            for (int t2 = 0; t2 < 2; t2++) {
                int row = wn * 32 + t2 * 16 + lrow;
                ldsm4(bf[t2], bb + (uint32_t)(row * 128 + ((chunk ^ (row & 7)) << 4)));
            }
            #pragma unroll
            for (int tm = 0; tm < 2; tm++)
                #pragma unroll
                for (int tn = 0; tn < 4; tn++)
                    mma_bf16(acc[tm][tn],
                             af[tm][0], af[tm][1], af[tm][2], af[tm][3],
                             bf[tn >> 1][tn & 1], bf[tn >> 1][2 + (tn & 1)]);
        }
    }
}

// stage a 128x128 bf16 row-major matrix into 2 swizzled kblocks (512 threads)
static __device__ __forceinline__ void stage128(
    uint32_t dst, const __nv_bfloat16* src, int tid)
{
    #pragma unroll
    for (int it = 0; it < 4; it++) {
        int idx = tid + (it << 9);
        int r = idx >> 4, q = idx & 15;
        int kblk = q >> 3, qi = q & 7;
        uint32_t off = (uint32_t)((r << 7) | (qi << 4));
        off ^= (off >> 3) & 0x70;
        cpa16(dst + (uint32_t)kblk * 16384u + off, src + (size_t)r * 128 + q * 8);
    }
}

// stage MLP weight chunk c: W1 rows [c*128, ...) and W2 cols [c*128, ...)
static __device__ __forceinline__ void mlp_stage_w(
    uint32_t wbuf, const __nv_bfloat16* W1, const __nv_bfloat16* W2, int c, int tid)
{
    const int nc0 = c * 128;
    #pragma unroll
    for (int it = 0; it < 4; it++) {
        int idx = tid + (it << 9);
        int r = idx >> 4, q = idx & 15;
        int kblk = q >> 3, qi = q & 7;
        uint32_t off = (uint32_t)((r << 7) | (qi << 4));
        off ^= (off >> 3) & 0x70;
        cpa16(wbuf + (uint32_t)kblk * 16384u + off,            W1 + (size_t)(nc0 + r) * 128 + q * 8);
        cpa16(wbuf + 32768u + (uint32_t)kblk * 16384u + off,   W2 + (size_t)r * 512 + nc0 + q * 8);
    }
    asm volatile("cp.async.commit_group;" ::: "memory");
}

// in-kernel LayerNorm of one 128-row tile into swizzled A smem (16 warps)
static __device__ __forceinline__ void ln_tile(
    uint32_t A_B, const float* __restrict__ xin,
    const float* __restrict__ gam, const float* __restrict__ bet,
    int m0, int wid, int lane)
{
    float4 g4 = *(const float4*)(gam + lane * 4);
    float4 b4 = *(const float4*)(bet + lane * 4);
    const uint32_t kblk = (lane >= 16) ? 16384u : 0u;
    uint32_t boff0 = (uint32_t)((lane * 4 & 63) * 2);
    #pragma unroll 4
    for (int it = 0; it < 8; it++) {
        const int row = it * 16 + wid;
        const int t = m0 + row;
        int w = t >> 6, n = t & 63;
        int b = w >> 8, wrem = w & 255;
        int wi = wrem >> 4, wj = wrem & 15;
        int y  = (wi * 8 + (n >> 3) + 4) & 127;
        int xc = (wj * 8 + (n & 7) + 4) & 127;
        size_t src = ((size_t)b << 14) + (size_t)y * 128 + xc;
        float4 v = *(const float4*)(xin + src * 128 + lane * 4);
        float s  = v.x + v.y + v.z + v.w;
        float sq = v.x * v.x + v.y * v.y + v.z * v.z + v.w * v.w;
        #pragma unroll
        for (int o = 16; o; o >>= 1) {
            s  += __shfl_xor_sync(0xffffffffu, s,  o);
            sq += __shfl_xor_sync(0xffffffffu, sq, o);
        }
        float mean = s * (1.f / 128.f);
        float rstd = rsqrtf(sq * (1.f / 128.f) - mean * mean + 1e-5f);
        uint32_t u0 = packbf((v.x - mean) * rstd * g4.x + b4.x,
                             (v.y - mean) * rstd * g4.y + b4.y);
        uint32_t u1 = packbf((v.z - mean) * rstd * g4.z + b4.z,
                             (v.w - mean) * rstd * g4.w + b4.w);
        uint32_t boff = (uint32_t)(row << 7) + boff0;
        boff ^= (boff >> 3) & 0x70;
        asm volatile("st.shared.v2.b32 [%0], {%1, %2};"
                     :: "r"(A_B + kblk + boff), "r"(u0), "r"(u1) : "memory");
    }
}

// ---------------- mega kernel: full Swin block per 128-token CTA --------------
#define FSMEM 225296
__device__ __forceinline__ int reg3(int y) { return y < 120 ? 0 : (y < 124 ? 1 : 2); }

__global__ __launch_bounds__(512) void swin_fused(
    const float* __restrict__ x, const float* __restrict__ n1g,
    const float* __restrict__ n1b, const unsigned short* __restrict__ wqu,
    const float* __restrict__ qkv_b, const unsigned short* __restrict__ wpu,
    const float* __restrict__ proj_b, const float* __restrict__ rpb,
    const float* __restrict__ n2g, const float* __restrict__ n2b,
    const unsigned short* __restrict__ w1u, const float* __restrict__ b1,
    const unsigned short* __restrict__ w2u, const float* __restrict__ b2,
    float* __restrict__ out)
{
    extern __shared__ char dsm[];
    const __nv_bfloat16* wq = (const __nv_bfloat16*)wqu;
    const __nv_bfloat16* wp = (const __nv_bfloat16*)wpu;
    const __nv_bfloat16* W1 = (const __nv_bfloat16*)w1u;
    const __nv_bfloat16* W2 = (const __nv_bfloat16*)w2u;
    const uint32_t s0 = smem_u32(dsm);
    const uint32_t A_B = s0;
    const uint32_t Q_B = s0 + 32768u;
    const uint32_t W_B = s0 + 155648u;
    const uint32_t HID = s0 + 32768u;
    float* rpbs = (float*)(dsm + 221184);
    int*   rgt  = (int*)(dsm + 224784);
    float* red  = (float*)(dsm + 221184);   // reused after attention
    const int tid = threadIdx.x, lane = tid & 31, wid = tid >> 5;
    const int wm = wid >> 2, wn = wid & 3;
    const int m0 = blockIdx.x * 128;
    const int lrow = (lane & 7) + ((lane >> 3) & 1) * 8;
    const int lhi  = lane >> 4;

    stage128(W_B, wq, tid);
    asm volatile("cp.async.commit_group;" ::: "memory");

    ln_tile(A_B, x, n1g, n1b, m0, wid, lane);

    for (int i = tid; i < 900; i += 512) rpbs[i] = rpb[i];
    if (tid < 128) {
        int lw = tid >> 6, n = tid & 63;
        int w = (m0 >> 6) + lw, wrem = w & 255;
        int wi = wrem >> 4, wj = wrem & 15;
        rgt[tid] = 3 * reg3(wi * 8 + (n >> 3)) + reg3(wj * 8 + (n & 7));
    }

    // ---- phase 1: QKV GEMM, 3 chunks of N=128 ----
    for (int c = 0; c < 3; c++) {
        if (c < 2) {
            stage128(W_B + (uint32_t)((c + 1) & 1) * 32768u, wq + (size_t)(c + 1) * 128 * 128, tid);
            asm volatile("cp.async.commit_group;" ::: "memory");
            asm volatile("cp.async.wait_group 1;" ::: "memory");
        } else {
            asm volatile("cp.async.wait_group 0;" ::: "memory");
        }
        __syncthreads();

        float acc[2][4][4];
        #pragma unroll
        for (int a = 0; a < 2; a++)
            #pragma unroll
            for (int b = 0; b < 4; b++)
                #pragma unroll
                for (int q = 0; q < 4; q++) acc[a][b][q] = 0.f;
        gemm128(A_B, W_B + (uint32_t)(c & 1) * 32768u, acc, wm, wn, lrow, lhi);

        float2 bs[4];
        #pragma unroll
        for (int tn = 0; tn < 4; tn++)
            bs[tn] = *(const float2*)(qkv_b + c * 128 + wn * 32 + tn * 8 + (lane & 3) * 2);
        const uint32_t slice = Q_B + (uint32_t)(c * 4 + wn) * 10240u;
        #pragma unroll
        for (int tm = 0; tm < 2; tm++) {
            #pragma unroll
            for (int h8 = 0; h8 < 2; h8++) {
                const int row = wm * 32 + tm * 16 + (lane >> 2) + h8 * 8;
                #pragma unroll
                for (int tn = 0; tn < 4; tn++) {
                    const int c32 = tn * 8 + (lane & 3) * 2;
                    float v0 = acc[tm][tn][h8 * 2 + 0] + bs[tn].x;
                    float v1 = acc[tm][tn][h8 * 2 + 1] + bs[tn].y;
                    asm volatile("st.shared.b32 [%0], %1;"
                                 :: "r"(slice + (uint32_t)(row * 80 + c32 * 2)),
                                    "r"(packbf(v0, v1)) : "memory");
                }
            }
        }
        __syncthreads();
    }

    // prefetch proj weights (group P)
    stage128(W_B + 32768u, wp, tid);
    asm volatile("cp.async.commit_group;" ::: "memory");

    // ---- phase 2: attention (16 warps: window, head-pair, row-quarter) ----
    {
        const int lw  = wid >> 3;
        const int hp  = (wid >> 2) & 1;
        const int wm4 = wid & 3;
        const uint32_t lh16 = (uint32_t)lhi * 16u;
        const uint32_t rowbase = (uint32_t)(lw * 64) * 80u;
        const int r0 = wm4 * 16 + (lane >> 2), r1 = r0 + 8;
        const int rg0 = rgt[lw * 64 + r0], rg1 = rgt[lw * 64 + r1];
        const int i1a = r0 >> 3, j1a = r0 & 7, i1b = r1 >> 3, j1b = r1 & 7;
        const int c0 = (lane & 3) * 2;
        const float scale = 0.17677669529663689f;

        const int wthis = (m0 >> 6) + lw;
        const int wtr = wthis & 255;
        const bool edge = ((wtr >> 4) == 15) || ((wtr & 15) == 15);

        const float* pb0 = rpbs + (size_t)((i1a * 15 + j1a + 112 - c0) * 4);
        const float* pb1 = rpbs + (size_t)((i1b * 15 + j1b + 112 - c0) * 4);

        #pragma unroll 1
        for (int hh = 0; hh < 2; hh++) {
            const int h = hp * 2 + hh;
            const uint32_t qsl = Q_B + (uint32_t)(0 + h) * 10240u + rowbase;
            const uint32_t ksl = Q_B + (uint32_t)(4 + h) * 10240u + rowbase;
            const uint32_t vsl = Q_B + (uint32_t)(8 + h) * 10240u + rowbase;
            const float* pbh0 = pb0 + h;
            const float* pbh1 = pb1 + h;

            uint32_t qa[2][4];
            {
                uint32_t addr = qsl + (uint32_t)((wm4 * 16 + lrow) * 80) + lh16;
                ldsm4(qa[0], addr);
                ldsm4(qa[1], addr + 32);
            }
            uint32_t kf[4][2][4];
            #pragma unroll
            for (int nt = 0; nt < 4; nt++) {
                uint32_t addr = ksl + (uint32_t)((nt * 16 + lrow) * 80) + lh16;
                ldsm4(kf[nt][0], addr);
                ldsm4(kf[nt][1], addr + 32);
            }

            float sc[8][4];
            #pragma unroll
            for (int i = 0; i < 8; i++)
                #pragma unroll
                for (int q = 0; q < 4; q++) sc[i][q] = 0.f;
            #pragma unroll
            for (int nt8 = 0; nt8 < 8; nt8++) {
                const int nt = nt8 >> 1, ii = nt8 & 1;
                mma_bf16(sc[nt8], qa[0][0], qa[0][1], qa[0][2], qa[0][3],
                         kf[nt][0][ii], kf[nt][0][2 + ii]);
                mma_bf16(sc[nt8], qa[1][0], qa[1][1], qa[1][2], qa[1][3],
                         kf[nt][1][ii], kf[nt][1][2 + ii]);
            }

            if (!edge) {
                #pragma unroll
                for (int nt8 = 0; nt8 < 8; nt8++) {
                    sc[nt8][0] = fmaf(sc[nt8][0], scale, pbh0[-nt8 * 60]);
                    sc[nt8][1] = fmaf(sc[nt8][1], scale, pbh0[-nt8 * 60 - 4]);
                    sc[nt8][2] = fmaf(sc[nt8][2], scale, pbh1[-nt8 * 60]);
                    sc[nt8][3] = fmaf(sc[nt8][3], scale, pbh1[-nt8 * 60 - 4]);
                }
            } else {
                const int* rg = rgt + lw * 64;
                #pragma unroll
                for (int nt8 = 0; nt8 < 8; nt8++) {
                    const int colb = nt8 * 8 + c0;
                    int rga = rg[colb], rgb = rg[colb + 1];
                    float v0 = fmaf(sc[nt8][0], scale, pbh0[-nt8 * 60]);
                    float v1 = fmaf(sc[nt8][1], scale, pbh0[-nt8 * 60 - 4]);
                    float v2 = fmaf(sc[nt8][2], scale, pbh1[-nt8 * 60]);
                    float v3 = fmaf(sc[nt8][3], scale, pbh1[-nt8 * 60 - 4]);
                    if (rga != rg0) v0 -= 100.f;
                    if (rgb != rg0) v1 -= 100.f;
                    if (rga != rg1) v2 -= 100.f;
                    if (rgb != rg1) v3 -= 100.f;
                    sc[nt8][0] = v0; sc[nt8][1] = v1; sc[nt8][2] = v2; sc[nt8][3] = v3;
                }
            }

            float mx0 = -1e30f, mx1 = -1e30f;
            #pragma unroll
            for (int nt8 = 0; nt8 < 8; nt8++) {
                mx0 = fmaxf(mx0, fmaxf(sc[nt8][0], sc[nt8][1]));
                mx1 = fmaxf(mx1, fmaxf(sc[nt8][2], sc[nt8][3]));
            }
            #pragma unroll
            for (int o = 1; o <= 2; o <<= 1) {
                mx0 = fmaxf(mx0, __shfl_xor_sync(0xffffffffu, mx0, o));
                mx1 = fmaxf(mx1, __shfl_xor_sync(0xffffffffu, mx1, o));
            }
            float sm0 = 0.f, sm1 = 0.f;
            #pragma unroll
            for (int nt8 = 0; nt8 < 8; nt8++) {
                sc[nt8][0] = __expf(sc[nt8][0] - mx0);
                sc[nt8][1] = __expf(sc[nt8][1] - mx0);
                sc[nt8][2] = __expf(sc[nt8][2] - mx1);
                sc[nt8][3] = __expf(sc[nt8][3] - mx1);
                sm0 += sc[nt8][0] + sc[nt8][1];
                sm1 += sc[nt8][2] + sc[nt8][3];
            }
            #pragma unroll
            for (int o = 1; o <= 2; o <<= 1) {
                sm0 += __shfl_xor_sync(0xffffffffu, sm0, o);
                sm1 += __shfl_xor_sync(0xffffffffu, sm1, o);
            }
            const float inv0 = 1.f / sm0, inv1 = 1.f / sm1;

            float oc[4][4];
            #pragma unroll
            for (int nt = 0; nt < 4; nt++)
                #pragma unroll
                for (int q = 0; q < 4; q++) oc[nt][q] = 0.f;
            #pragma unroll
            for (int kc = 0; kc < 4; kc++) {
                const uint32_t a0 = packbf(sc[2 * kc][0],     sc[2 * kc][1]);
                const uint32_t a1 = packbf(sc[2 * kc][2],     sc[2 * kc][3]);
                const uint32_t a2 = packbf(sc[2 * kc + 1][0], sc[2 * kc + 1][1]);
                const uint32_t a3 = packbf(sc[2 * kc + 1][2], sc[2 * kc + 1][3]);
                uint32_t vf0[4], vf1[4];
                const uint32_t vaddr = vsl + (uint32_t)((kc * 16 + lrow) * 80) + lh16;
                ldsm4t(vf0, vaddr);
                ldsm4t(vf1, vaddr + 32);
                mma_bf16(oc[0], a0, a1, a2, a3, vf0[0], vf0[1]);
                mma_bf16(oc[1], a0, a1, a2, a3, vf0[2], vf0[3]);
                mma_bf16(oc[2], a0, a1, a2, a3, vf1[0], vf1[1]);
                mma_bf16(oc[3], a0, a1, a2, a3, vf1[2], vf1[3]);
            }

            #pragma unroll
            for (int nt = 0; nt < 4; nt++) {
                const int ch = h * 32 + nt * 8 + c0;
                const uint32_t kblk = (uint32_t)(ch >> 6) * 16384u;
                uint32_t b0 = (uint32_t)(((lw * 64 + r0) << 7) + ((ch & 63) << 1));
                uint32_t b1 = (uint32_t)(((lw * 64 + r1) << 7) + ((ch & 63) << 1));
                b0 ^= (b0 >> 3) & 0x70;
                b1 ^= (b1 >> 3) & 0x70;
                asm volatile("st.shared.b32 [%0], %1;" ::
                    "r"(A_B + kblk + b0), "r"(packbf(oc[nt][0] * inv0, oc[nt][1] * inv0)) : "memory");
                asm volatile("st.shared.b32 [%0], %1;" ::
                    "r"(A_B + kblk + b1), "r"(packbf(oc[nt][2] * inv1, oc[nt][3] * inv1)) : "memory");
            }
        }
    }
    __syncthreads();   // attn outputs in A_B; Q_B now dead

    // prefetch MLP weight chunk 0 into pool (Q_B region; group M0)
    mlp_stage_w(Q_B + 32768u, W1, W2, 0, tid);
    asm volatile("cp.async.wait_group 1;" ::: "memory");  // proj weights (P) ready
    __syncthreads();

    // ---- phase 3: proj GEMM; x1 kept in registers ----
    float xv[2][4][4];
    {
        #pragma unroll
        for (int a = 0; a < 2; a++)
            #pragma unroll
            for (int b = 0; b < 4; b++)
                #pragma unroll
                for (int q = 0; q < 4; q++) xv[a][b][q] = 0.f;
        gemm128(A_B, W_B + 32768u, xv, wm, wn, lrow, lhi);

        float2 bs[4];
        #pragma unroll
        for (int tn = 0; tn < 4; tn++)
            bs[tn] = *(const float2*)(proj_b + wn * 32 + tn * 8 + (lane & 3) * 2);
        #pragma unroll
        for (int tm = 0; tm < 2; tm++) {
            #pragma unroll
            for (int h8 = 0; h8 < 2; h8++) {
                const int m = m0 + wm * 32 + tm * 16 + (lane >> 2) + h8 * 8;
                int w = m >> 6, nt2 = m & 63;
                int b = w >> 8, wrem = w & 255;
                int wwi = wrem >> 4, wwj = wrem & 15;
                int yf = (wwi * 8 + (nt2 >> 3) + 4) & 127;
                int xf = (wwj * 8 + (nt2 & 7) + 4) & 127;
                size_t mo = ((size_t)b << 14) + (size_t)yf * 128 + xf;
                float s = 0.f, sq = 0.f;
                #pragma unroll
                for (int tn = 0; tn < 4; tn++) {
                    const int nn = wn * 32 + tn * 8 + (lane & 3) * 2;
                    float2 r2 = *(const float2*)(x + mo * 128 + nn);
                    float v0 = xv[tm][tn][h8 * 2 + 0] + bs[tn].x + r2.x;
                    float v1 = xv[tm][tn][h8 * 2 + 1] + bs[tn].y + r2.y;
                    xv[tm][tn][h8 * 2 + 0] = v0;
                    xv[tm][tn][h8 * 2 + 1] = v1;
                    s += v0 + v1;
                    sq += v0 * v0 + v1 * v1;
                }
                #pragma unroll
                for (int o = 1; o <= 2; o <<= 1) {
                    s  += __shfl_xor_sync(0xffffffffu, s,  o);
                    sq += __shfl_xor_sync(0xffffffffu, sq, o);
                }
                if ((lane & 3) == 0) {
                    const int rloc = wm * 32 + tm * 16 + (lane >> 2) + h8 * 8;
                    red[rloc * 8 + wn * 2 + 0] = s;
                    red[rloc * 8 + wn * 2 + 1] = sq;
                }
            }
        }
    }
    __syncthreads();

    // ---- phase 4: LN2 from registers -> A_B (bf16 swizzled) ----
    #pragma unroll
    for (int tm = 0; tm < 2; tm++) {
        #pragma unroll
        for (int h8 = 0; h8 < 2; h8++) {
            const int rloc = wm * 32 + tm * 16 + (lane >> 2) + h8 * 8;
            float4 p0 = *(const float4*)(red + rloc * 8);
            float4 p1 = *(const float4*)(red + rloc * 8 + 4);
            float s  = p0.x + p0.z + p1.x + p1.z;
            float sq = p0.y + p0.w + p1.y + p1.w;
            float mean = s * (1.f / 128.f);
            float rstd = rsqrtf(sq * (1.f / 128.f) - mean * mean + 1e-5f);
            #pragma unroll
            for (int tn = 0; tn < 4; tn++) {
                const int nn = wn * 32 + tn * 8 + (lane & 3) * 2;
                float2 gg = *(const float2*)(n2g + nn);
                float2 bb = *(const float2*)(n2b + nn);
                float v0 = (xv[tm][tn][h8 * 2 + 0] - mean) * rstd * gg.x + bb.x;
                float v1 = (xv[tm][tn][h8 * 2 + 1] - mean) * rstd * gg.y + bb.y;
                const uint32_t kblk = (uint32_t)(nn >> 6) * 16384u;
                uint32_t boff = (uint32_t)((rloc << 7) + ((nn & 63) << 1));
                boff ^= (boff >> 3) & 0x70;
                asm volatile("st.shared.b32 [%0], %1;"
                             :: "r"(A_B + kblk + boff), "r"(packbf(v0, v1)) : "memory");
            }
        }
    }
    __syncthreads();

    // ---- phase 5: MLP loop (hid @ HID, weights double-buffered in pool) ----
    float acc2[2][4][4];
    #pragma unroll
    for (int a = 0; a < 2; a++)
        #pragma unroll
        for (int b = 0; b < 4; b++)
            #pragma unroll
            for (int q = 0; q < 4; q++) acc2[a][b][q] = 0.f;

    for (int c = 0; c < 4; c++) {
        if (c + 1 < 4) {
            mlp_stage_w(Q_B + 32768u + (uint32_t)((c + 1) & 1) * 65536u, W1, W2, c + 1, tid);
            asm volatile("cp.async.wait_group 1;" ::: "memory");
        } else {
            asm volatile("cp.async.wait_group 0;" ::: "memory");
        }
        __syncthreads();

        const uint32_t wb = Q_B + 32768u + (uint32_t)(c & 1) * 65536u;

        float acc1[2][4][4];
        #pragma unroll
        for (int a = 0; a < 2; a++)
            #pragma unroll
            for (int b = 0; b < 4; b++)
                #pragma unroll
                for (int q = 0; q < 4; q++) acc1[a][b][q] = 0.f;
        gemm128(A_B, wb, acc1, wm, wn, lrow, lhi);

        {
            float2 bs1[4];
            #pragma unroll
            for (int tn = 0; tn < 4; tn++)
                bs1[tn] = *(const float2*)(b1 + c * 128 + wn * 32 + tn * 8 + (lane & 3) * 2);
            #pragma unroll
            for (int tm = 0; tm < 2; tm++) {
                #pragma unroll
                for (int h = 0; h < 2; h++) {
                    const int row = wm * 32 + tm * 16 + (lane >> 2) + h * 8;
                    #pragma unroll
                    for (int tn = 0; tn < 4; tn++) {
                        const int nn = wn * 32 + tn * 8 + (lane & 3) * 2;
                        float v0 = gelu_fast(acc1[tm][tn][h * 2 + 0] + bs1[tn].x);
                        float v1 = gelu_fast(acc1[tm][tn][h * 2 + 1] + bs1[tn].y);
                        uint32_t boff = (uint32_t)((row << 7) + (nn & 63) * 2);
                        boff ^= (boff >> 3) & 0x70;
                        uint32_t dst = HID + ((nn >= 64) ? 16384u : 0u) + boff;
                        asm volatile("st.shared.b32 [%0], %1;" :: "r"(dst), "r"(packbf(v0, v1)) : "memory");
                    }
                }
            }
        }
        __syncthreads();

        gemm128(HID, wb + 32768u, acc2, wm, wn, lrow, lhi);
        __syncthreads();
    }

    // ---- epilogue: out = acc2 + b2 + x1(regs), scattered ----
    float2 bs[4];
    #pragma unroll
    for (int tn = 0; tn < 4; tn++)
        bs[tn] = *(const float2*)(b2 + wn * 32 + tn * 8 + (lane & 3) * 2);
    #pragma unroll
    for (int tm = 0; tm < 2; tm++) {
        #pragma unroll
        for (int h8 = 0; h8 < 2; h8++) {
            const int m = m0 + wm * 32 + tm * 16 + (lane >> 2) + h8 * 8;
            int w = m >> 6, nt2 = m & 63;
            int b = w >> 8, wrem = w & 255;
            int wwi = wrem >> 4, wwj = wrem & 15;
            int yf = (wwi * 8 + (nt2 >> 3) + 4) & 127;
            int xf = (wwj * 8 + (nt2 & 7) + 4) & 127;
            size_t mo = ((size_t)b << 14) + (size_t)yf * 128 + xf;
            #pragma unroll
            for (int tn = 0; tn < 4; tn++) {
                const int nn = wn * 32 + tn * 8 + (lane & 3) * 2;
                float v0 = acc2[tm][tn][h8 * 2 + 0] + bs[tn].x + xv[tm][tn][h8 * 2 + 0];
                float v1 = acc2[tm][tn][h8 * 2 + 1] + bs[tn].y + xv[tm][tn][h8 * 2 + 1];
                *(float2*)(out + mo * 128 + nn) = make_float2(v0, v1);
            }
        }
    }
}

// ---------------- launch ----------------
extern "C" void kernel_launch(void* const* d_in, const int* in_sizes, int n_in,
                              void* d_out, int out_size)
{
    const float* x      = (const float*)d_in[0];
    const float* rpb    = (const float*)d_in[1];
    const float* n1g    = (const float*)d_in[2];
    const float* n1b    = (const float*)d_in[3];
    const float* qkv_w  = (const float*)d_in[4];
    const float* qkv_b  = (const float*)d_in[5];
    const float* proj_w = (const float*)d_in[6];
    const float* proj_b = (const float*)d_in[7];
    const float* n2g    = (const float*)d_in[8];
    const float* n2b    = (const float*)d_in[9];
    const float* fc1_w  = (const float*)d_in[10];
    const float* fc1_b  = (const float*)d_in[11];
    const float* fc2_w  = (const float*)d_in[12];
    const float* fc2_b  = (const float*)d_in[13];
    float* out = (float*)d_out;

    unsigned short *wq, *wp, *w1, *w2;
    cudaGetSymbolAddress((void**)&wq,  g_wq);
    cudaGetSymbolAddress((void**)&wp,  g_wp);
    cudaGetSymbolAddress((void**)&w1,  g_w1);
    cudaGetSymbolAddress((void**)&w2,  g_w2);

    cudaFuncSetAttribute(swin_fused, cudaFuncAttributeMaxDynamicSharedMemorySize, FSMEM);

    f2bf_all<<<192, 256>>>(qkv_w, wq, proj_w, wp, fc1_w, w1, fc2_w, w2);

    swin_fused<<<MTOK / 128, 512, FSMEM>>>(x, n1g, n1b, wq, qkv_b, wp, proj_b, rpb,
                                           n2g, n2b, w1, fc1_b, w2, fc2_b, out);
}

// round 15
// speedup vs baseline: 1.1863x; 1.0087x over previous
#include <cuda_runtime.h>
#include <cuda_bf16.h>
#include <math.h>
#include <stdint.h>

// B=8, H=W=128, C=128, HEADS=4, d=32, WS=8, SHIFT=4, HIDDEN=512
#define MTOK 131072

// ---------------- scratch (device globals; no allocs allowed) ----------------
static __device__ unsigned short g_wq[384 * 128];
static __device__ unsigned short g_wp[128 * 128];
static __device__ unsigned short g_w1[512 * 128];
static __device__ unsigned short g_w2[128 * 512];

// ---------------- PTX helpers (sm_80+ features only) ----------------
static __device__ __forceinline__ uint32_t smem_u32(const void* p) {
    uint32_t a;
    asm("{ .reg .u64 t; cvta.to.shared.u64 t, %1; cvt.u32.u64 %0, t; }" : "=r"(a) : "l"(p));
    return a;
}
static __device__ __forceinline__ void cpa16(uint32_t s, const void* g) {
    asm volatile("cp.async.cg.shared.global [%0], [%1], 16;" :: "r"(s), "l"(g) : "memory");
}
static __device__ __forceinline__ void ldsm4(uint32_t* r, uint32_t addr) {
    asm volatile("ldmatrix.sync.aligned.m8n8.x4.shared.b16 {%0,%1,%2,%3}, [%4];"
                 : "=r"(r[0]), "=r"(r[1]), "=r"(r[2]), "=r"(r[3]) : "r"(addr));
}
static __device__ __forceinline__ void ldsm4t(uint32_t* r, uint32_t addr) {
    asm volatile("ldmatrix.sync.aligned.m8n8.x4.trans.shared.b16 {%0,%1,%2,%3}, [%4];"
                 : "=r"(r[0]), "=r"(r[1]), "=r"(r[2]), "=r"(r[3]) : "r"(addr));
}
static __device__ __forceinline__ void mma_bf16(float* c,
    uint32_t a0, uint32_t a1, uint32_t a2, uint32_t a3, uint32_t b0, uint32_t b1) {
    asm volatile(
        "mma.sync.aligned.m16n8k16.row.col.f32.bf16.bf16.f32 "
        "{%0,%1,%2,%3}, {%4,%5,%6,%7}, {%8,%9}, {%0,%1,%2,%3};"
        : "+f"(c[0]), "+f"(c[1]), "+f"(c[2]), "+f"(c[3])
        : "r"(a0), "r"(a1), "r"(a2), "r"(a3), "r"(b0), "r"(b1));
}
static __device__ __forceinline__ uint32_t packbf(float a, float b) {
    __nv_bfloat162 p = __floats2bfloat162_rn(a, b);
    return *reinterpret_cast<uint32_t*>(&p);
}
// tanh-form GELU via sigmoid: x * sigma(2*0.79788456*(x + 0.044715 x^3))
static __device__ __forceinline__ float gelu_fast(float v) {
    float a = 1.5957691216057308f * fmaf(0.044715f * v, v * v, v);
    return __fdividef(v, 1.f + __expf(-a));
}

// ---------------- merged fp32 -> bf16 weight conversion ----------------
__global__ __launch_bounds__(256) void f2bf_all(
    const float* __restrict__ s0, unsigned short* __restrict__ d0,
    const float* __restrict__ s1, unsigned short* __restrict__ d1,
    const float* __restrict__ s2, unsigned short* __restrict__ d2,
    const float* __restrict__ s3, unsigned short* __restrict__ d3)
{
    int i = blockIdx.x * 256 + threadIdx.x;
    const float* s; unsigned short* d; int o;
    if (i < 12288)      { s = s0; d = d0; o = i; }
    else if (i < 16384) { s = s1; d = d1; o = i - 12288; }
    else if (i < 32768) { s = s2; d = d2; o = i - 16384; }
    else                { s = s3; d = d3; o = i - 32768; }
    float4 v = ((const float4*)s)[o];
    uint2 u;
    u.x = packbf(v.x, v.y);
    u.y = packbf(v.z, v.w);
    ((uint2*)d)[o] = u;
}

// ------------- 16-warp GEMM core: C128x128 += A(2 kblk) @ B(2 kblk)^T ---------
static __device__ __forceinline__ void gemm128(
    uint32_t abase, uint32_t bbase, float acc[2][4][4],
    int wm, int wn, int lrow, int lhi)
{
    #pragma unroll
    for (int kb = 0; kb < 2; kb++) {
        const uint32_t ab = abase + (uint32_t)kb * 16384u;
        const uint32_t bb = bbase + (uint32_t)kb * 16384u;
        #pragma unroll
        for (int ks = 0; ks < 4; ks++) {
            uint32_t af[2][4], bf[2][4];
            const int chunk = ks * 2 + lhi;
            #pragma unroll
            for (int tm = 0; tm < 2; tm++) {
                int row = wm * 32 + tm * 16 + lrow;
                ldsm4(af[tm], ab + (uint32_t)(row * 128 + ((chunk ^ (row & 7)) << 4)));
            }
            #pragma unroll
            for (int t2 = 0; t2 < 2; t2++) {
                int row = wn * 32 + t2 * 16 + lrow;
                ldsm4(bf[t2], bb + (uint32_t)(row * 128 + ((chunk ^ (row & 7)) << 4)));
            }
            #pragma unroll
            for (int tm = 0; tm < 2; tm++)
                #pragma unroll
                for (int tn = 0; tn < 4; tn++)
                    mma_bf16(acc[tm][tn],
                             af[tm][0], af[tm][1], af[tm][2], af[tm][3],
                             bf[tn >> 1][tn & 1], bf[tn >> 1][2 + (tn & 1)]);
        }
    }
}

// stage a 128x128 bf16 row-major matrix into 2 swizzled kblocks (512 threads)
static __device__ __forceinline__ void stage128(
    uint32_t dst, const __nv_bfloat16* src, int tid)
{
    #pragma unroll
    for (int it = 0; it < 4; it++) {
        int idx = tid + (it << 9);
        int r = idx >> 4, q = idx & 15;
        int kblk = q >> 3, qi = q & 7;
        uint32_t off = (uint32_t)((r << 7) | (qi << 4));
        off ^= (off >> 3) & 0x70;
        cpa16(dst + (uint32_t)kblk * 16384u + off, src + (size_t)r * 128 + q * 8);
    }
}

// stage MLP weight chunk c: W1 rows [c*128, ...) and W2 cols [c*128, ...)
static __device__ __forceinline__ void mlp_stage_w(
    uint32_t wbuf, const __nv_bfloat16* W1, const __nv_bfloat16* W2, int c, int tid)
{
    const int nc0 = c * 128;
    #pragma unroll
    for (int it = 0; it < 4; it++) {
        int idx = tid + (it << 9);
        int r = idx >> 4, q = idx & 15;
        int kblk = q >> 3, qi = q & 7;
        uint32_t off = (uint32_t)((r << 7) | (qi << 4));
        off ^= (off >> 3) & 0x70;
        cpa16(wbuf + (uint32_t)kblk * 16384u + off,            W1 + (size_t)(nc0 + r) * 128 + q * 8);
        cpa16(wbuf + 32768u + (uint32_t)kblk * 16384u + off,   W2 + (size_t)r * 512 + nc0 + q * 8);
    }
    asm volatile("cp.async.commit_group;" ::: "memory");
}

// in-kernel LayerNorm of one 128-row tile into swizzled A smem (16 warps)
static __device__ __forceinline__ void ln_tile(
    uint32_t A_B, const float* __restrict__ xin,
    const float* __restrict__ gam, const float* __restrict__ bet,
    int m0, int wid, int lane)
{
    float4 g4 = *(const float4*)(gam + lane * 4);
    float4 b4 = *(const float4*)(bet + lane * 4);
    const uint32_t kblk = (lane >= 16) ? 16384u : 0u;
    uint32_t boff0 = (uint32_t)((lane * 4 & 63) * 2);
    #pragma unroll 4
    for (int it = 0; it < 8; it++) {
        const int row = it * 16 + wid;
        const int t = m0 + row;
        int w = t >> 6, n = t & 63;
        int b = w >> 8, wrem = w & 255;
        int wi = wrem >> 4, wj = wrem & 15;
        int y  = (wi * 8 + (n >> 3) + 4) & 127;
        int xc = (wj * 8 + (n & 7) + 4) & 127;
        size_t src = ((size_t)b << 14) + (size_t)y * 128 + xc;
        float4 v = *(const float4*)(xin + src * 128 + lane * 4);
        float s  = v.x + v.y + v.z + v.w;
        float sq = v.x * v.x + v.y * v.y + v.z * v.z + v.w * v.w;
        #pragma unroll
        for (int o = 16; o; o >>= 1) {
            s  += __shfl_xor_sync(0xffffffffu, s,  o);
            sq += __shfl_xor_sync(0xffffffffu, sq, o);
        }
        float mean = s * (1.f / 128.f);
        float rstd = rsqrtf(sq * (1.f / 128.f) - mean * mean + 1e-5f);
        uint32_t u0 = packbf((v.x - mean) * rstd * g4.x + b4.x,
                             (v.y - mean) * rstd * g4.y + b4.y);
        uint32_t u1 = packbf((v.z - mean) * rstd * g4.z + b4.z,
                             (v.w - mean) * rstd * g4.w + b4.w);
        uint32_t boff = (uint32_t)(row << 7) + boff0;
        boff ^= (boff >> 3) & 0x70;
        asm volatile("st.shared.v2.b32 [%0], {%1, %2};"
                     :: "r"(A_B + kblk + boff), "r"(u0), "r"(u1) : "memory");
    }
}

// ---------------- mega kernel: full Swin block per 128-token CTA --------------
#define FSMEM 225296
__device__ __forceinline__ int reg3(int y) { return y < 120 ? 0 : (y < 124 ? 1 : 2); }

__global__ __launch_bounds__(512) void swin_fused(
    const float* __restrict__ x, const float* __restrict__ n1g,
    const float* __restrict__ n1b, const unsigned short* __restrict__ wqu,
    const float* __restrict__ qkv_b, const unsigned short* __restrict__ wpu,
    const float* __restrict__ proj_b, const float* __restrict__ rpb,
    const float* __restrict__ n2g, const float* __restrict__ n2b,
    const unsigned short* __restrict__ w1u, const float* __restrict__ b1,
    const unsigned short* __restrict__ w2u, const float* __restrict__ b2,
    float* __restrict__ out)
{
    extern __shared__ char dsm[];
    const __nv_bfloat16* wq = (const __nv_bfloat16*)wqu;
    const __nv_bfloat16* wp = (const __nv_bfloat16*)wpu;
    const __nv_bfloat16* W1 = (const __nv_bfloat16*)w1u;
    const __nv_bfloat16* W2 = (const __nv_bfloat16*)w2u;
    const uint32_t s0 = smem_u32(dsm);
    const uint32_t A_B = s0;
    const uint32_t Q_B = s0 + 32768u;
    const uint32_t W_B = s0 + 155648u;
    const uint32_t HID = s0 + 32768u;
    float* rpbs = (float*)(dsm + 221184);
    int*   rgt  = (int*)(dsm + 224784);
    float* red  = (float*)(dsm + 221184);   // reused after attention
    const int tid = threadIdx.x, lane = tid & 31, wid = tid >> 5;
    const int wm = wid >> 2, wn = wid & 3;
    const int m0 = blockIdx.x * 128;
    const int lrow = (lane & 7) + ((lane >> 3) & 1) * 8;
    const int lhi  = lane >> 4;
    const float LOG2E = 1.4426950408889634f;

    stage128(W_B, wq, tid);
    asm volatile("cp.async.commit_group;" ::: "memory");

    ln_tile(A_B, x, n1g, n1b, m0, wid, lane);

    // stage rpb pre-scaled by log2e (softmax runs in log2 domain)
    for (int i = tid; i < 900; i += 512) rpbs[i] = rpb[i] * LOG2E;
    if (tid < 128) {
        int lw = tid >> 6, n = tid & 63;
        int w = (m0 >> 6) + lw, wrem = w & 255;
        int wi = wrem >> 4, wj = wrem & 15;
        rgt[tid] = 3 * reg3(wi * 8 + (n >> 3)) + reg3(wj * 8 + (n & 7));
    }

    // ---- phase 1: QKV GEMM, 3 chunks of N=128 ----
    for (int c = 0; c < 3; c++) {
        if (c < 2) {
            stage128(W_B + (uint32_t)((c + 1) & 1) * 32768u, wq + (size_t)(c + 1) * 128 * 128, tid);
            asm volatile("cp.async.commit_group;" ::: "memory");
            asm volatile("cp.async.wait_group 1;" ::: "memory");
        } else {
            asm volatile("cp.async.wait_group 0;" ::: "memory");
        }
        __syncthreads();

        float acc[2][4][4];
        #pragma unroll
        for (int a = 0; a < 2; a++)
            #pragma unroll
            for (int b = 0; b < 4; b++)
                #pragma unroll
                for (int q = 0; q < 4; q++) acc[a][b][q] = 0.f;
        gemm128(A_B, W_B + (uint32_t)(c & 1) * 32768u, acc, wm, wn, lrow, lhi);

        float2 bs[4];
        #pragma unroll
        for (int tn = 0; tn < 4; tn++)
            bs[tn] = *(const float2*)(qkv_b + c * 128 + wn * 32 + tn * 8 + (lane & 3) * 2);
        const uint32_t slice = Q_B + (uint32_t)(c * 4 + wn) * 10240u;
        #pragma unroll
        for (int tm = 0; tm < 2; tm++) {
            #pragma unroll
            for (int h8 = 0; h8 < 2; h8++) {
                const int row = wm * 32 + tm * 16 + (lane >> 2) + h8 * 8;
                #pragma unroll
                for (int tn = 0; tn < 4; tn++) {
                    const int c32 = tn * 8 + (lane & 3) * 2;
                    float v0 = acc[tm][tn][h8 * 2 + 0] + bs[tn].x;
                    float v1 = acc[tm][tn][h8 * 2 + 1] + bs[tn].y;
                    asm volatile("st.shared.b32 [%0], %1;"
                                 :: "r"(slice + (uint32_t)(row * 80 + c32 * 2)),
                                    "r"(packbf(v0, v1)) : "memory");
                }
            }
        }
        __syncthreads();
    }

    // prefetch proj weights (group P)
    stage128(W_B + 32768u, wp, tid);
    asm volatile("cp.async.commit_group;" ::: "memory");

    // ---- phase 2: attention (16 warps: window, head-pair, row-quarter) ----
    {
        const int lw  = wid >> 3;
        const int hp  = (wid >> 2) & 1;
        const int wm4 = wid & 3;
        const uint32_t lh16 = (uint32_t)lhi * 16u;
        const uint32_t rowbase = (uint32_t)(lw * 64) * 80u;
        const int r0 = wm4 * 16 + (lane >> 2), r1 = r0 + 8;
        const int rg0 = rgt[lw * 64 + r0], rg1 = rgt[lw * 64 + r1];
        const int i1a = r0 >> 3, j1a = r0 & 7, i1b = r1 >> 3, j1b = r1 & 7;
        const int c0 = (lane & 3) * 2;
        const float scale = 0.17677669529663689f * 1.4426950408889634f; // log2 domain

        const int wthis = (m0 >> 6) + lw;
        const int wtr = wthis & 255;
        const bool edge = ((wtr >> 4) == 15) || ((wtr & 15) == 15);

        const float* pb0 = rpbs + (size_t)((i1a * 15 + j1a + 112 - c0) * 4);
        const float* pb1 = rpbs + (size_t)((i1b * 15 + j1b + 112 - c0) * 4);

        #pragma unroll 1
        for (int hh = 0; hh < 2; hh++) {
            const int h = hp * 2 + hh;
            const uint32_t qsl = Q_B + (uint32_t)(0 + h) * 10240u + rowbase;
            const uint32_t ksl = Q_B + (uint32_t)(4 + h) * 10240u + rowbase;
            const uint32_t vsl = Q_B + (uint32_t)(8 + h) * 10240u + rowbase;
            const float* pbh0 = pb0 + h;
            const float* pbh1 = pb1 + h;

            uint32_t qa[2][4];
            {
                uint32_t addr = qsl + (uint32_t)((wm4 * 16 + lrow) * 80) + lh16;
                ldsm4(qa[0], addr);
                ldsm4(qa[1], addr + 32);
            }
            uint32_t kf[4][2][4];
            #pragma unroll
            for (int nt = 0; nt < 4; nt++) {
                uint32_t addr = ksl + (uint32_t)((nt * 16 + lrow) * 80) + lh16;
                ldsm4(kf[nt][0], addr);
                ldsm4(kf[nt][1], addr + 32);
            }

            float sc[8][4];
            #pragma unroll
            for (int i = 0; i < 8; i++)
                #pragma unroll
                for (int q = 0; q < 4; q++) sc[i][q] = 0.f;
            #pragma unroll
            for (int nt8 = 0; nt8 < 8; nt8++) {
                const int nt = nt8 >> 1, ii = nt8 & 1;
                mma_bf16(sc[nt8], qa[0][0], qa[0][1], qa[0][2], qa[0][3],
                         kf[nt][0][ii], kf[nt][0][2 + ii]);
                mma_bf16(sc[nt8], qa[1][0], qa[1][1], qa[1][2], qa[1][3],
                         kf[nt][1][ii], kf[nt][1][2 + ii]);
            }

            if (!edge) {
                #pragma unroll
                for (int nt8 = 0; nt8 < 8; nt8++) {
                    sc[nt8][0] = fmaf(sc[nt8][0], scale, pbh0[-nt8 * 60]);
                    sc[nt8][1] = fmaf(sc[nt8][1], scale, pbh0[-nt8 * 60 - 4]);
                    sc[nt8][2] = fmaf(sc[nt8][2], scale, pbh1[-nt8 * 60]);
                    sc[nt8][3] = fmaf(sc[nt8][3], scale, pbh1[-nt8 * 60 - 4]);
                }
            } else {
                const int* rg = rgt + lw * 64;
                #pragma unroll
                for (int nt8 = 0; nt8 < 8; nt8++) {
                    const int colb = nt8 * 8 + c0;
                    int rga = rg[colb], rgb = rg[colb + 1];
                    float v0 = fmaf(sc[nt8][0], scale, pbh0[-nt8 * 60]);
                    float v1 = fmaf(sc[nt8][1], scale, pbh0[-nt8 * 60 - 4]);
                    float v2 = fmaf(sc[nt8][2], scale, pbh1[-nt8 * 60]);
                    float v3 = fmaf(sc[nt8][3], scale, pbh1[-nt8 * 60 - 4]);
                    if (rga != rg0) v0 -= 144.269504088896f;
                    if (rgb != rg0) v1 -= 144.269504088896f;
                    if (rga != rg1) v2 -= 144.269504088896f;
                    if (rgb != rg1) v3 -= 144.269504088896f;
                    sc[nt8][0] = v0; sc[nt8][1] = v1; sc[nt8][2] = v2; sc[nt8][3] = v3;
                }
            }

            // softmax without max-subtract (|scores| << 88, overflow-safe)
            float sm0 = 0.f, sm1 = 0.f;
            #pragma unroll
            for (int nt8 = 0; nt8 < 8; nt8++) {
                sc[nt8][0] = exp2f(sc[nt8][0]);
                sc[nt8][1] = exp2f(sc[nt8][1]);
                sc[nt8][2] = exp2f(sc[nt8][2]);
                sc[nt8][3] = exp2f(sc[nt8][3]);
                sm0 += sc[nt8][0] + sc[nt8][1];
                sm1 += sc[nt8][2] + sc[nt8][3];
            }
            #pragma unroll
            for (int o = 1; o <= 2; o <<= 1) {
                sm0 += __shfl_xor_sync(0xffffffffu, sm0, o);
                sm1 += __shfl_xor_sync(0xffffffffu, sm1, o);
            }
            const float inv0 = 1.f / sm0, inv1 = 1.f / sm1;

            float oc[4][4];
            #pragma unroll
            for (int nt = 0; nt < 4; nt++)
                #pragma unroll
                for (int q = 0; q < 4; q++) oc[nt][q] = 0.f;
            #pragma unroll
            for (int kc = 0; kc < 4; kc++) {
                const uint32_t a0 = packbf(sc[2 * kc][0],     sc[2 * kc][1]);
                const uint32_t a1 = packbf(sc[2 * kc][2],     sc[2 * kc][3]);
                const uint32_t a2 = packbf(sc[2 * kc + 1][0], sc[2 * kc + 1][1]);
                const uint32_t a3 = packbf(sc[2 * kc + 1][2], sc[2 * kc + 1][3]);
                uint32_t vf0[4], vf1[4];
                const uint32_t vaddr = vsl + (uint32_t)((kc * 16 + lrow) * 80) + lh16;
                ldsm4t(vf0, vaddr);
                ldsm4t(vf1, vaddr + 32);
                mma_bf16(oc[0], a0, a1, a2, a3, vf0[0], vf0[1]);
                mma_bf16(oc[1], a0, a1, a2, a3, vf0[2], vf0[3]);
                mma_bf16(oc[2], a0, a1, a2, a3, vf1[0], vf1[1]);
                mma_bf16(oc[3], a0, a1, a2, a3, vf1[2], vf1[3]);
            }

            #pragma unroll
            for (int nt = 0; nt < 4; nt++) {
                const int ch = h * 32 + nt * 8 + c0;
                const uint32_t kblk = (uint32_t)(ch >> 6) * 16384u;
                uint32_t b0 = (uint32_t)(((lw * 64 + r0) << 7) + ((ch & 63) << 1));
                uint32_t b1 = (uint32_t)(((lw * 64 + r1) << 7) + ((ch & 63) << 1));
                b0 ^= (b0 >> 3) & 0x70;
                b1 ^= (b1 >> 3) & 0x70;
                asm volatile("st.shared.b32 [%0], %1;" ::
                    "r"(A_B + kblk + b0), "r"(packbf(oc[nt][0] * inv0, oc[nt][1] * inv0)) : "memory");
                asm volatile("st.shared.b32 [%0], %1;" ::
                    "r"(A_B + kblk + b1), "r"(packbf(oc[nt][2] * inv1, oc[nt][3] * inv1)) : "memory");
            }
        }
    }
    __syncthreads();   // attn outputs in A_B; Q_B now dead

    // prefetch MLP weight chunk 0 into pool (Q_B region; group M0)
    mlp_stage_w(Q_B + 32768u, W1, W2, 0, tid);
    asm volatile("cp.async.wait_group 1;" ::: "memory");  // proj weights (P) ready
    __syncthreads();

    // ---- phase 3: proj GEMM; x1 kept in registers ----
    float xv[2][4][4];
    {
        #pragma unroll
        for (int a = 0; a < 2; a++)
            #pragma unroll
            for (int b = 0; b < 4; b++)
                #pragma unroll
                for (int q = 0; q < 4; q++) xv[a][b][q] = 0.f;
        gemm128(A_B, W_B + 32768u, xv, wm, wn, lrow, lhi);

        float2 bs[4];
        #pragma unroll
        for (int tn = 0; tn < 4; tn++)
            bs[tn] = *(const float2*)(proj_b + wn * 32 + tn * 8 + (lane & 3) * 2);
        #pragma unroll
        for (int tm = 0; tm < 2; tm++) {
            #pragma unroll
            for (int h8 = 0; h8 < 2; h8++) {
                const int m = m0 + wm * 32 + tm * 16 + (lane >> 2) + h8 * 8;
                int w = m >> 6, nt2 = m & 63;
                int b = w >> 8, wrem = w & 255;
                int wwi = wrem >> 4, wwj = wrem & 15;
                int yf = (wwi * 8 + (nt2 >> 3) + 4) & 127;
                int xf = (wwj * 8 + (nt2 & 7) + 4) & 127;
                size_t mo = ((size_t)b << 14) + (size_t)yf * 128 + xf;
                float s = 0.f, sq = 0.f;
                #pragma unroll
                for (int tn = 0; tn < 4; tn++) {
                    const int nn = wn * 32 + tn * 8 + (lane & 3) * 2;
                    float2 r2 = *(const float2*)(x + mo * 128 + nn);
                    float v0 = xv[tm][tn][h8 * 2 + 0] + bs[tn].x + r2.x;
                    float v1 = xv[tm][tn][h8 * 2 + 1] + bs[tn].y + r2.y;
                    xv[tm][tn][h8 * 2 + 0] = v0;
                    xv[tm][tn][h8 * 2 + 1] = v1;
                    s += v0 + v1;
                    sq += v0 * v0 + v1 * v1;
                }
                #pragma unroll
                for (int o = 1; o <= 2; o <<= 1) {
                    s  += __shfl_xor_sync(0xffffffffu, s,  o);
                    sq += __shfl_xor_sync(0xffffffffu, sq, o);
                }
                if ((lane & 3) == 0) {
                    const int rloc = wm * 32 + tm * 16 + (lane >> 2) + h8 * 8;
                    red[rloc * 8 + wn * 2 + 0] = s;
                    red[rloc * 8 + wn * 2 + 1] = sq;
                }
            }
        }
    }
    __syncthreads();

    // ---- phase 4: LN2 from registers -> A_B (bf16 swizzled) ----
    #pragma unroll
    for (int tm = 0; tm < 2; tm++) {
        #pragma unroll
        for (int h8 = 0; h8 < 2; h8++) {
            const int rloc = wm * 32 + tm * 16 + (lane >> 2) + h8 * 8;
            float4 p0 = *(const float4*)(red + rloc * 8);
            float4 p1 = *(const float4*)(red + rloc * 8 + 4);
            float s  = p0.x + p0.z + p1.x + p1.z;
            float sq = p0.y + p0.w + p1.y + p1.w;
            float mean = s * (1.f / 128.f);
            float rstd = rsqrtf(sq * (1.f / 128.f) - mean * mean + 1e-5f);
            #pragma unroll
            for (int tn = 0; tn < 4; tn++) {
                const int nn = wn * 32 + tn * 8 + (lane & 3) * 2;
                float2 gg = *(const float2*)(n2g + nn);
                float2 bb = *(const float2*)(n2b + nn);
                float v0 = (xv[tm][tn][h8 * 2 + 0] - mean) * rstd * gg.x + bb.x;
                float v1 = (xv[tm][tn][h8 * 2 + 1] - mean) * rstd * gg.y + bb.y;
                const uint32_t kblk = (uint32_t)(nn >> 6) * 16384u;
                uint32_t boff = (uint32_t)((rloc << 7) + ((nn & 63) << 1));
                boff ^= (boff >> 3) & 0x70;
                asm volatile("st.shared.b32 [%0], %1;"
                             :: "r"(A_B + kblk + boff), "r"(packbf(v0, v1)) : "memory");
            }
        }
    }
    __syncthreads();

    // ---- phase 5: MLP loop (hid @ HID, weights double-buffered in pool) ----
    float acc2[2][4][4];
    #pragma unroll
    for (int a = 0; a < 2; a++)
        #pragma unroll
        for (int b = 0; b < 4; b++)
            #pragma unroll
            for (int q = 0; q < 4; q++) acc2[a][b][q] = 0.f;

    for (int c = 0; c < 4; c++) {
        if (c + 1 < 4) {
            mlp_stage_w(Q_B + 32768u + (uint32_t)((c + 1) & 1) * 65536u, W1, W2, c + 1, tid);
            asm volatile("cp.async.wait_group 1;" ::: "memory");
        } else {
            asm volatile("cp.async.wait_group 0;" ::: "memory");
        }
        __syncthreads();

        const uint32_t wb = Q_B + 32768u + (uint32_t)(c & 1) * 65536u;

        float acc1[2][4][4];
        #pragma unroll
        for (int a = 0; a < 2; a++)
            #pragma unroll
            for (int b = 0; b < 4; b++)
                #pragma unroll
                for (int q = 0; q < 4; q++) acc1[a][b][q] = 0.f;
        gemm128(A_B, wb, acc1, wm, wn, lrow, lhi);

        {
            float2 bs1[4];
            #pragma unroll
            for (int tn = 0; tn < 4; tn++)
                bs1[tn] = *(const float2*)(b1 + c * 128 + wn * 32 + tn * 8 + (lane & 3) * 2);
            #pragma unroll
            for (int tm = 0; tm < 2; tm++) {
                #pragma unroll
                for (int h = 0; h < 2; h++) {
                    const int row = wm * 32 + tm * 16 + (lane >> 2) + h * 8;
                    #pragma unroll
                    for (int tn = 0; tn < 4; tn++) {
                        const int nn = wn * 32 + tn * 8 + (lane & 3) * 2;
                        float v0 = gelu_fast(acc1[tm][tn][h * 2 + 0] + bs1[tn].x);
                        float v1 = gelu_fast(acc1[tm][tn][h * 2 + 1] + bs1[tn].y);
                        uint32_t boff = (uint32_t)((row << 7) + (nn & 63) * 2);
                        boff ^= (boff >> 3) & 0x70;
                        uint32_t dst = HID + ((nn >= 64) ? 16384u : 0u) + boff;
                        asm volatile("st.shared.b32 [%0], %1;" :: "r"(dst), "r"(packbf(v0, v1)) : "memory");
                    }
                }
            }
        }
        __syncthreads();

        gemm128(HID, wb + 32768u, acc2, wm, wn, lrow, lhi);
        __syncthreads();
    }

    // ---- epilogue: out = acc2 + b2 + x1(regs), scattered ----
    float2 bs[4];
    #pragma unroll
    for (int tn = 0; tn < 4; tn++)
        bs[tn] = *(const float2*)(b2 + wn * 32 + tn * 8 + (lane & 3) * 2);
    #pragma unroll
    for (int tm = 0; tm < 2; tm++) {
        #pragma unroll
        for (int h8 = 0; h8 < 2; h8++) {
            const int m = m0 + wm * 32 + tm * 16 + (lane >> 2) + h8 * 8;
            int w = m >> 6, nt2 = m & 63;
            int b = w >> 8, wrem = w & 255;
            int wwi = wrem >> 4, wwj = wrem & 15;
            int yf = (wwi * 8 + (nt2 >> 3) + 4) & 127;
            int xf = (wwj * 8 + (nt2 & 7) + 4) & 127;
            size_t mo = ((size_t)b << 14) + (size_t)yf * 128 + xf;
            #pragma unroll
            for (int tn = 0; tn < 4; tn++) {
                const int nn = wn * 32 + tn * 8 + (lane & 3) * 2;
                float v0 = acc2[tm][tn][h8 * 2 + 0] + bs[tn].x + xv[tm][tn][h8 * 2 + 0];
                float v1 = acc2[tm][tn][h8 * 2 + 1] + bs[tn].y + xv[tm][tn][h8 * 2 + 1];
                *(float2*)(out + mo * 128 + nn) = make_float2(v0, v1);
            }
        }
    }
}

// ---------------- launch ----------------
extern "C" void kernel_launch(void* const* d_in, const int* in_sizes, int n_in,
                              void* d_out, int out_size)
{
    const float* x      = (const float*)d_in[0];
    const float* rpb    = (const float*)d_in[1];
    const float* n1g    = (const float*)d_in[2];
    const float* n1b    = (const float*)d_in[3];
    const float* qkv_w  = (const float*)d_in[4];
    const float* qkv_b  = (const float*)d_in[5];
    const float* proj_w = (const float*)d_in[6];
    const float* proj_b = (const float*)d_in[7];
    const float* n2g    = (const float*)d_in[8];
    const float* n2b    = (const float*)d_in[9];
    const float* fc1_w  = (const float*)d_in[10];
    const float* fc1_b  = (const float*)d_in[11];
    const float* fc2_w  = (const float*)d_in[12];
    const float* fc2_b  = (const float*)d_in[13];
    float* out = (float*)d_out;

    unsigned short *wq, *wp, *w1, *w2;
    cudaGetSymbolAddress((void**)&wq,  g_wq);
    cudaGetSymbolAddress((void**)&wp,  g_wp);
    cudaGetSymbolAddress((void**)&w1,  g_w1);
    cudaGetSymbolAddress((void**)&w2,  g_w2);

    cudaFuncSetAttribute(swin_fused, cudaFuncAttributeMaxDynamicSharedMemorySize, FSMEM);

    f2bf_all<<<192, 256>>>(qkv_w, wq, proj_w, wp, fc1_w, w1, fc2_w, w2);

    swin_fused<<<MTOK / 128, 512, FSMEM>>>(x, n1g, n1b, wq, qkv_b, wp, proj_b, rpb,
                                           n2g, n2b, w1, fc1_b, w2, fc2_b, out);
}

// round 16
// speedup vs baseline: 1.2688x; 1.0696x over previous
#include <cuda_runtime.h>
#include <cuda_bf16.h>
#include <math.h>
#include <stdint.h>

// B=8, H=W=128, C=128, HEADS=4, d=32, WS=8, SHIFT=4, HIDDEN=512
#define MTOK 131072

// ---------------- scratch (device globals; no allocs allowed) ----------------
static __device__ unsigned short g_wq[384 * 128];
static __device__ unsigned short g_wp[128 * 128];
static __device__ unsigned short g_w1[512 * 128];
static __device__ unsigned short g_w2[128 * 512];

// ---------------- PTX helpers (sm_80+ features only) ----------------
static __device__ __forceinline__ uint32_t smem_u32(const void* p) {
    uint32_t a;
    asm("{ .reg .u64 t; cvta.to.shared.u64 t, %1; cvt.u32.u64 %0, t; }" : "=r"(a) : "l"(p));
    return a;
}
static __device__ __forceinline__ void cpa16(uint32_t s, const void* g) {
    asm volatile("cp.async.cg.shared.global [%0], [%1], 16;" :: "r"(s), "l"(g) : "memory");
}
static __device__ __forceinline__ void ldsm4(uint32_t* r, uint32_t addr) {
    asm volatile("ldmatrix.sync.aligned.m8n8.x4.shared.b16 {%0,%1,%2,%3}, [%4];"
                 : "=r"(r[0]), "=r"(r[1]), "=r"(r[2]), "=r"(r[3]) : "r"(addr));
}
static __device__ __forceinline__ void ldsm4t(uint32_t* r, uint32_t addr) {
    asm volatile("ldmatrix.sync.aligned.m8n8.x4.trans.shared.b16 {%0,%1,%2,%3}, [%4];"
                 : "=r"(r[0]), "=r"(r[1]), "=r"(r[2]), "=r"(r[3]) : "r"(addr));
}
static __device__ __forceinline__ void mma_bf16(float* c,
    uint32_t a0, uint32_t a1, uint32_t a2, uint32_t a3, uint32_t b0, uint32_t b1) {
    asm volatile(
        "mma.sync.aligned.m16n8k16.row.col.f32.bf16.bf16.f32 "
        "{%0,%1,%2,%3}, {%4,%5,%6,%7}, {%8,%9}, {%0,%1,%2,%3};"
        : "+f"(c[0]), "+f"(c[1]), "+f"(c[2]), "+f"(c[3])
        : "r"(a0), "r"(a1), "r"(a2), "r"(a3), "r"(b0), "r"(b1));
}
static __device__ __forceinline__ uint32_t packbf(float a, float b) {
    __nv_bfloat162 p = __floats2bfloat162_rn(a, b);
    return *reinterpret_cast<uint32_t*>(&p);
}
// tanh-form GELU via sigmoid
static __device__ __forceinline__ float gelu_fast(float v) {
    float a = 1.5957691216057308f * fmaf(0.044715f * v, v * v, v);
    return __fdividef(v, 1.f + __expf(-a));
}

// ---------------- merged fp32 -> bf16 weight conversion ----------------
__global__ __launch_bounds__(256) void f2bf_all(
    const float* __restrict__ s0, unsigned short* __restrict__ d0,
    const float* __restrict__ s1, unsigned short* __restrict__ d1,
    const float* __restrict__ s2, unsigned short* __restrict__ d2,
    const float* __restrict__ s3, unsigned short* __restrict__ d3)
{
    int i = blockIdx.x * 256 + threadIdx.x;
    const float* s; unsigned short* d; int o;
    if (i < 12288)      { s = s0; d = d0; o = i; }
    else if (i < 16384) { s = s1; d = d1; o = i - 12288; }
    else if (i < 32768) { s = s2; d = d2; o = i - 16384; }
    else                { s = s3; d = d3; o = i - 32768; }
    float4 v = ((const float4*)s)[o];
    uint2 u;
    u.x = packbf(v.x, v.y);
    u.y = packbf(v.z, v.w);
    ((uint2*)d)[o] = u;
}

// ------------- 8-warp GEMM core: C64x128 += A64(2x8K kblk) @ B128(2x16K)^T ----
static __device__ __forceinline__ void gemm64(
    uint32_t abase, uint32_t bbase, float acc[2][4][4],
    int wm, int wn, int lrow, int lhi)
{
    #pragma unroll
    for (int kb = 0; kb < 2; kb++) {
        const uint32_t ab = abase + (uint32_t)kb * 8192u;
        const uint32_t bb = bbase + (uint32_t)kb * 16384u;
        #pragma unroll
        for (int ks = 0; ks < 4; ks++) {
            uint32_t af[2][4], bf[2][4];
            const int chunk = ks * 2 + lhi;
            #pragma unroll
            for (int tm = 0; tm < 2; tm++) {
                int row = wm * 32 + tm * 16 + lrow;
                ldsm4(af[tm], ab + (uint32_t)(row * 128 + ((chunk ^ (row & 7)) << 4)));
            }
            #pragma unroll
            for (int t2 = 0; t2 < 2; t2++) {
                int row = wn * 32 + t2 * 16 + lrow;
                ldsm4(bf[t2], bb + (uint32_t)(row * 128 + ((chunk ^ (row & 7)) << 4)));
            }
            #pragma unroll
            for (int tm = 0; tm < 2; tm++)
                #pragma unroll
                for (int tn = 0; tn < 4; tn++)
                    mma_bf16(acc[tm][tn],
                             af[tm][0], af[tm][1], af[tm][2], af[tm][3],
                             bf[tn >> 1][tn & 1], bf[tn >> 1][2 + (tn & 1)]);
        }
    }
}

// stage a 128x128 bf16 weight (2 x 16KB kblocks), 256 threads
static __device__ __forceinline__ void stage_w128(
    uint32_t dst, const __nv_bfloat16* src, int tid)
{
    #pragma unroll
    for (int it = 0; it < 8; it++) {
        int idx = tid + (it << 8);
        int r = idx >> 4, q = idx & 15;
        int kblk = q >> 3, qi = q & 7;
        uint32_t off = (uint32_t)((r << 7) | (qi << 4));
        off ^= (off >> 3) & 0x70;
        cpa16(dst + (uint32_t)kblk * 16384u + off, src + (size_t)r * 128 + q * 8);
    }
    asm volatile("cp.async.commit_group;" ::: "memory");
}

// stage MLP weight chunk c: W1 rows [c*128..) and W2 cols [c*128..)
static __device__ __forceinline__ void mlp_stage_w(
    uint32_t wbuf, const __nv_bfloat16* W1, const __nv_bfloat16* W2, int c, int tid)
{
    const int nc0 = c * 128;
    #pragma unroll
    for (int it = 0; it < 8; it++) {
        int idx = tid + (it << 8);
        int r = idx >> 4, q = idx & 15;
        int kblk = q >> 3, qi = q & 7;
        uint32_t off = (uint32_t)((r << 7) | (qi << 4));
        off ^= (off >> 3) & 0x70;
        cpa16(wbuf + (uint32_t)kblk * 16384u + off,            W1 + (size_t)(nc0 + r) * 128 + q * 8);
        cpa16(wbuf + 32768u + (uint32_t)kblk * 16384u + off,   W2 + (size_t)r * 512 + nc0 + q * 8);
    }
    asm volatile("cp.async.commit_group;" ::: "memory");
}

// in-kernel LN of one 64-row tile into swizzled A smem (8 warps, kblk 8192)
static __device__ __forceinline__ void ln_tile64(
    uint32_t A_B, const float* __restrict__ xin,
    const float* __restrict__ gam, const float* __restrict__ bet,
    int m0, int wid, int lane)
{
    float4 g4 = *(const float4*)(gam + lane * 4);
    float4 b4 = *(const float4*)(bet + lane * 4);
    const uint32_t kblk = (lane >= 16) ? 8192u : 0u;
    uint32_t boff0 = (uint32_t)((lane * 4 & 63) * 2);
    #pragma unroll 4
    for (int it = 0; it < 8; it++) {
        const int row = it * 8 + wid;
        const int t = m0 + row;
        int w = t >> 6, n = t & 63;
        int b = w >> 8, wrem = w & 255;
        int wi = wrem >> 4, wj = wrem & 15;
        int y  = (wi * 8 + (n >> 3) + 4) & 127;
        int xc = (wj * 8 + (n & 7) + 4) & 127;
        size_t src = ((size_t)b << 14) + (size_t)y * 128 + xc;
        float4 v = *(const float4*)(xin + src * 128 + lane * 4);
        float s  = v.x + v.y + v.z + v.w;
        float sq = v.x * v.x + v.y * v.y + v.z * v.z + v.w * v.w;
        #pragma unroll
        for (int o = 16; o; o >>= 1) {
            s  += __shfl_xor_sync(0xffffffffu, s,  o);
            sq += __shfl_xor_sync(0xffffffffu, sq, o);
        }
        float mean = s * (1.f / 128.f);
        float rstd = rsqrtf(sq * (1.f / 128.f) - mean * mean + 1e-5f);
        uint32_t u0 = packbf((v.x - mean) * rstd * g4.x + b4.x,
                             (v.y - mean) * rstd * g4.y + b4.y);
        uint32_t u1 = packbf((v.z - mean) * rstd * g4.z + b4.z,
                             (v.w - mean) * rstd * g4.w + b4.w);
        uint32_t boff = (uint32_t)(row << 7) + boff0;
        boff ^= (boff >> 3) & 0x70;
        asm volatile("st.shared.v2.b32 [%0], {%1, %2};"
                     :: "r"(A_B + kblk + boff), "r"(u0), "r"(u1) : "memory");
    }
}

// ---------------- mega kernel: full Swin block per 64-token CTA (1 window) ----
// smem (114448 B):
//  A_B  [0, 16384)       LN1 tile -> attn out -> LN2 tile (kblk 8192)
//  Q_B  [16384, 77824)   12 qkv slices x 64 rows x 80B (5120 each)
//  W_B  [77824, 110592)  single 32KB weight buffer (qkv chunks, then proj)
//  MLP: HID @16384 (16KB, kblk 8192), WBUF @32768 (64KB: W1c+W2c)
//  AUX  [110592, 114448) rpb 3600B + rgt 256B ; red (2KB) reuses rpb area
#define FSMEM 114448
__device__ __forceinline__ int reg3(int y) { return y < 120 ? 0 : (y < 124 ? 1 : 2); }

__global__ __launch_bounds__(256, 2) void swin_fused(
    const float* __restrict__ x, const float* __restrict__ n1g,
    const float* __restrict__ n1b, const unsigned short* __restrict__ wqu,
    const float* __restrict__ qkv_b, const unsigned short* __restrict__ wpu,
    const float* __restrict__ proj_b, const float* __restrict__ rpb,
    const float* __restrict__ n2g, const float* __restrict__ n2b,
    const unsigned short* __restrict__ w1u, const float* __restrict__ b1,
    const unsigned short* __restrict__ w2u, const float* __restrict__ b2,
    float* __restrict__ out)
{
    extern __shared__ char dsm[];
    const __nv_bfloat16* wq = (const __nv_bfloat16*)wqu;
    const __nv_bfloat16* wp = (const __nv_bfloat16*)wpu;
    const __nv_bfloat16* W1 = (const __nv_bfloat16*)w1u;
    const __nv_bfloat16* W2 = (const __nv_bfloat16*)w2u;
    const uint32_t s0 = smem_u32(dsm);
    const uint32_t A_B = s0;
    const uint32_t Q_B = s0 + 16384u;
    const uint32_t W_B = s0 + 77824u;
    const uint32_t HID = s0 + 16384u;
    const uint32_t WBUF = s0 + 32768u;
    float* rpbs = (float*)(dsm + 110592);
    int*   rgt  = (int*)(dsm + 114192);
    float* red  = (float*)(dsm + 110592);   // reused after attention
    const int tid = threadIdx.x, lane = tid & 31, wid = tid >> 5;
    const int wm = wid >> 2, wn = wid & 3;
    const int m0 = blockIdx.x * 64;
    const int lrow = (lane & 7) + ((lane >> 3) & 1) * 8;
    const int lhi  = lane >> 4;
    const float LOG2E = 1.4426950408889634f;

    stage_w128(W_B, wq, tid);   // qkv chunk 0

    ln_tile64(A_B, x, n1g, n1b, m0, wid, lane);

    for (int i = tid; i < 900; i += 256) rpbs[i] = rpb[i] * LOG2E;
    if (tid < 64) {
        int w = m0 >> 6, wrem = w & 255;
        int wi = wrem >> 4, wj = wrem & 15;
        rgt[tid] = 3 * reg3(wi * 8 + (tid >> 3)) + reg3(wj * 8 + (tid & 7));
    }

    // ---- phase 1: QKV GEMM, 3 chunks of N=128 (single W buffer) ----
    for (int c = 0; c < 3; c++) {
        asm volatile("cp.async.wait_group 0;" ::: "memory");
        __syncthreads();

        float acc[2][4][4];
        #pragma unroll
        for (int a = 0; a < 2; a++)
            #pragma unroll
            for (int b = 0; b < 4; b++)
                #pragma unroll
                for (int q = 0; q < 4; q++) acc[a][b][q] = 0.f;
        gemm64(A_B, W_B, acc, wm, wn, lrow, lhi);

        float2 bs[4];
        #pragma unroll
        for (int tn = 0; tn < 4; tn++)
            bs[tn] = *(const float2*)(qkv_b + c * 128 + wn * 32 + tn * 8 + (lane & 3) * 2);
        const uint32_t slice = Q_B + (uint32_t)(c * 4 + wn) * 5120u;
        #pragma unroll
        for (int tm = 0; tm < 2; tm++) {
            #pragma unroll
            for (int h8 = 0; h8 < 2; h8++) {
                const int row = wm * 32 + tm * 16 + (lane >> 2) + h8 * 8;
                #pragma unroll
                for (int tn = 0; tn < 4; tn++) {
                    const int c32 = tn * 8 + (lane & 3) * 2;
                    float v0 = acc[tm][tn][h8 * 2 + 0] + bs[tn].x;
                    float v1 = acc[tm][tn][h8 * 2 + 1] + bs[tn].y;
                    asm volatile("st.shared.b32 [%0], %1;"
                                 :: "r"(slice + (uint32_t)(row * 80 + c32 * 2)),
                                    "r"(packbf(v0, v1)) : "memory");
                }
            }
        }
        __syncthreads();   // all W_B reads done
        if (c < 2) stage_w128(W_B, wq + (size_t)(c + 1) * 128 * 128, tid);
        else       stage_w128(W_B, wp, tid);   // proj weights, arrive during attn
    }

    // ---- phase 2: attention (8 warps: head-pair x row-quarter; 1 window) ----
    {
        const int hp  = wid >> 2;          // head pair 0/1
        const int wm4 = wid & 3;           // row quarter
        const uint32_t lh16 = (uint32_t)lhi * 16u;
        const int r0 = wm4 * 16 + (lane >> 2), r1 = r0 + 8;
        const int rg0 = rgt[r0], rg1 = rgt[r1];
        const int i1a = r0 >> 3, j1a = r0 & 7, i1b = r1 >> 3, j1b = r1 & 7;
        const int c0 = (lane & 3) * 2;
        const float scale = 0.17677669529663689f * 1.4426950408889634f;

        const int wtr = (m0 >> 6) & 255;
        const bool edge = ((wtr >> 4) == 15) || ((wtr & 15) == 15);

        const float* pb0 = rpbs + (size_t)((i1a * 15 + j1a + 112 - c0) * 4);
        const float* pb1 = rpbs + (size_t)((i1b * 15 + j1b + 112 - c0) * 4);

        #pragma unroll 1
        for (int hh = 0; hh < 2; hh++) {
            const int h = hp * 2 + hh;
            const uint32_t qsl = Q_B + (uint32_t)(0 + h) * 5120u;
            const uint32_t ksl = Q_B + (uint32_t)(4 + h) * 5120u;
            const uint32_t vsl = Q_B + (uint32_t)(8 + h) * 5120u;
            const float* pbh0 = pb0 + h;
            const float* pbh1 = pb1 + h;

            uint32_t qa[2][4];
            {
                uint32_t addr = qsl + (uint32_t)((wm4 * 16 + lrow) * 80) + lh16;
                ldsm4(qa[0], addr);
                ldsm4(qa[1], addr + 32);
            }
            uint32_t kf[4][2][4];
            #pragma unroll
            for (int nt = 0; nt < 4; nt++) {
                uint32_t addr = ksl + (uint32_t)((nt * 16 + lrow) * 80) + lh16;
                ldsm4(kf[nt][0], addr);
                ldsm4(kf[nt][1], addr + 32);
            }

            float sc[8][4];
            #pragma unroll
            for (int i = 0; i < 8; i++)
                #pragma unroll
                for (int q = 0; q < 4; q++) sc[i][q] = 0.f;
            #pragma unroll
            for (int nt8 = 0; nt8 < 8; nt8++) {
                const int nt = nt8 >> 1, ii = nt8 & 1;
                mma_bf16(sc[nt8], qa[0][0], qa[0][1], qa[0][2], qa[0][3],
                         kf[nt][0][ii], kf[nt][0][2 + ii]);
                mma_bf16(sc[nt8], qa[1][0], qa[1][1], qa[1][2], qa[1][3],
                         kf[nt][1][ii], kf[nt][1][2 + ii]);
            }

            if (!edge) {
                #pragma unroll
                for (int nt8 = 0; nt8 < 8; nt8++) {
                    sc[nt8][0] = fmaf(sc[nt8][0], scale, pbh0[-nt8 * 60]);
                    sc[nt8][1] = fmaf(sc[nt8][1], scale, pbh0[-nt8 * 60 - 4]);
                    sc[nt8][2] = fmaf(sc[nt8][2], scale, pbh1[-nt8 * 60]);
                    sc[nt8][3] = fmaf(sc[nt8][3], scale, pbh1[-nt8 * 60 - 4]);
                }
            } else {
                #pragma unroll
                for (int nt8 = 0; nt8 < 8; nt8++) {
                    const int colb = nt8 * 8 + c0;
                    int rga = rgt[colb], rgb = rgt[colb + 1];
                    float v0 = fmaf(sc[nt8][0], scale, pbh0[-nt8 * 60]);
                    float v1 = fmaf(sc[nt8][1], scale, pbh0[-nt8 * 60 - 4]);
                    float v2 = fmaf(sc[nt8][2], scale, pbh1[-nt8 * 60]);
                    float v3 = fmaf(sc[nt8][3], scale, pbh1[-nt8 * 60 - 4]);
                    if (rga != rg0) v0 -= 144.269504088896f;
                    if (rgb != rg0) v1 -= 144.269504088896f;
                    if (rga != rg1) v2 -= 144.269504088896f;
                    if (rgb != rg1) v3 -= 144.269504088896f;
                    sc[nt8][0] = v0; sc[nt8][1] = v1; sc[nt8][2] = v2; sc[nt8][3] = v3;
                }
            }

            float sm0 = 0.f, sm1 = 0.f;
            #pragma unroll
            for (int nt8 = 0; nt8 < 8; nt8++) {
                sc[nt8][0] = exp2f(sc[nt8][0]);
                sc[nt8][1] = exp2f(sc[nt8][1]);
                sc[nt8][2] = exp2f(sc[nt8][2]);
                sc[nt8][3] = exp2f(sc[nt8][3]);
                sm0 += sc[nt8][0] + sc[nt8][1];
                sm1 += sc[nt8][2] + sc[nt8][3];
            }
            #pragma unroll
            for (int o = 1; o <= 2; o <<= 1) {
                sm0 += __shfl_xor_sync(0xffffffffu, sm0, o);
                sm1 += __shfl_xor_sync(0xffffffffu, sm1, o);
            }
            const float inv0 = 1.f / sm0, inv1 = 1.f / sm1;

            float oc[4][4];
            #pragma unroll
            for (int nt = 0; nt < 4; nt++)
                #pragma unroll
                for (int q = 0; q < 4; q++) oc[nt][q] = 0.f;
            #pragma unroll
            for (int kc = 0; kc < 4; kc++) {
                const uint32_t a0 = packbf(sc[2 * kc][0],     sc[2 * kc][1]);
                const uint32_t a1 = packbf(sc[2 * kc][2],     sc[2 * kc][3]);
                const uint32_t a2 = packbf(sc[2 * kc + 1][0], sc[2 * kc + 1][1]);
                const uint32_t a3 = packbf(sc[2 * kc + 1][2], sc[2 * kc + 1][3]);
                uint32_t vf0[4], vf1[4];
                const uint32_t vaddr = vsl + (uint32_t)((kc * 16 + lrow) * 80) + lh16;
                ldsm4t(vf0, vaddr);
                ldsm4t(vf1, vaddr + 32);
                mma_bf16(oc[0], a0, a1, a2, a3, vf0[0], vf0[1]);
                mma_bf16(oc[1], a0, a1, a2, a3, vf0[2], vf0[3]);
                mma_bf16(oc[2], a0, a1, a2, a3, vf1[0], vf1[1]);
                mma_bf16(oc[3], a0, a1, a2, a3, vf1[2], vf1[3]);
            }

            #pragma unroll
            for (int nt = 0; nt < 4; nt++) {
                const int ch = h * 32 + nt * 8 + c0;
                const uint32_t kblk = (uint32_t)(ch >> 6) * 8192u;
                uint32_t b0 = (uint32_t)((r0 << 7) + ((ch & 63) << 1));
                uint32_t b1 = (uint32_t)((r1 << 7) + ((ch & 63) << 1));
                b0 ^= (b0 >> 3) & 0x70;
                b1 ^= (b1 >> 3) & 0x70;
                asm volatile("st.shared.b32 [%0], %1;" ::
                    "r"(A_B + kblk + b0), "r"(packbf(oc[nt][0] * inv0, oc[nt][1] * inv0)) : "memory");
                asm volatile("st.shared.b32 [%0], %1;" ::
                    "r"(A_B + kblk + b1), "r"(packbf(oc[nt][2] * inv1, oc[nt][3] * inv1)) : "memory");
            }
        }
    }
    asm volatile("cp.async.wait_group 0;" ::: "memory");   // proj weights ready
    __syncthreads();   // attn outputs visible; Q_B dead

    // ---- phase 3: proj GEMM; x1 kept in registers ----
    float xv[2][4][4];
    {
        #pragma unroll
        for (int a = 0; a < 2; a++)
            #pragma unroll
            for (int b = 0; b < 4; b++)
                #pragma unroll
                for (int q = 0; q < 4; q++) xv[a][b][q] = 0.f;
        gemm64(A_B, W_B, xv, wm, wn, lrow, lhi);

        float2 bs[4];
        #pragma unroll
        for (int tn = 0; tn < 4; tn++)
            bs[tn] = *(const float2*)(proj_b + wn * 32 + tn * 8 + (lane & 3) * 2);
        #pragma unroll
        for (int tm = 0; tm < 2; tm++) {
            #pragma unroll
            for (int h8 = 0; h8 < 2; h8++) {
                const int m = m0 + wm * 32 + tm * 16 + (lane >> 2) + h8 * 8;
                int w = m >> 6, nt2 = m & 63;
                int b = w >> 8, wrem = w & 255;
                int wwi = wrem >> 4, wwj = wrem & 15;
                int yf = (wwi * 8 + (nt2 >> 3) + 4) & 127;
                int xf = (wwj * 8 + (nt2 & 7) + 4) & 127;
                size_t mo = ((size_t)b << 14) + (size_t)yf * 128 + xf;
                float s = 0.f, sq = 0.f;
                #pragma unroll
                for (int tn = 0; tn < 4; tn++) {
                    const int nn = wn * 32 + tn * 8 + (lane & 3) * 2;
                    float2 r2 = *(const float2*)(x + mo * 128 + nn);
                    float v0 = xv[tm][tn][h8 * 2 + 0] + bs[tn].x + r2.x;
                    float v1 = xv[tm][tn][h8 * 2 + 1] + bs[tn].y + r2.y;
                    xv[tm][tn][h8 * 2 + 0] = v0;
                    xv[tm][tn][h8 * 2 + 1] = v1;
                    s += v0 + v1;
                    sq += v0 * v0 + v1 * v1;
                }
                #pragma unroll
                for (int o = 1; o <= 2; o <<= 1) {
                    s  += __shfl_xor_sync(0xffffffffu, s,  o);
                    sq += __shfl_xor_sync(0xffffffffu, sq, o);
                }
                if ((lane & 3) == 0) {
                    const int rloc = wm * 32 + tm * 16 + (lane >> 2) + h8 * 8;
                    red[rloc * 8 + wn * 2 + 0] = s;
                    red[rloc * 8 + wn * 2 + 1] = sq;
                }
            }
        }
    }
    __syncthreads();   // red visible; W_B reads done

    // stage MLP chunk 0 into WBUF (overlaps dead W_B region — safe now)
    mlp_stage_w(WBUF, W1, W2, 0, tid);

    // ---- phase 4: LN2 from registers -> A_B (bf16 swizzled, kblk 8192) ----
    #pragma unroll
    for (int tm = 0; tm < 2; tm++) {
        #pragma unroll
        for (int h8 = 0; h8 < 2; h8++) {
            const int rloc = wm * 32 + tm * 16 + (lane >> 2) + h8 * 8;
            float4 p0 = *(const float4*)(red + rloc * 8);
            float4 p1 = *(const float4*)(red + rloc * 8 + 4);
            float s  = p0.x + p0.z + p1.x + p1.z;
            float sq = p0.y + p0.w + p1.y + p1.w;
            float mean = s * (1.f / 128.f);
            float rstd = rsqrtf(sq * (1.f / 128.f) - mean * mean + 1e-5f);
            #pragma unroll
            for (int tn = 0; tn < 4; tn++) {
                const int nn = wn * 32 + tn * 8 + (lane & 3) * 2;
                float2 gg = *(const float2*)(n2g + nn);
                float2 bb = *(const float2*)(n2b + nn);
                float v0 = (xv[tm][tn][h8 * 2 + 0] - mean) * rstd * gg.x + bb.x;
                float v1 = (xv[tm][tn][h8 * 2 + 1] - mean) * rstd * gg.y + bb.y;
                const uint32_t kblk = (uint32_t)(nn >> 6) * 8192u;
                uint32_t boff = (uint32_t)((rloc << 7) + ((nn & 63) << 1));
                boff ^= (boff >> 3) & 0x70;
                asm volatile("st.shared.b32 [%0], %1;"
                             :: "r"(A_B + kblk + boff), "r"(packbf(v0, v1)) : "memory");
            }
        }
    }

    // ---- phase 5: MLP loop (single WBUF, HID @16384) ----
    float acc2[2][4][4];
    #pragma unroll
    for (int a = 0; a < 2; a++)
        #pragma unroll
        for (int b = 0; b < 4; b++)
            #pragma unroll
            for (int q = 0; q < 4; q++) acc2[a][b][q] = 0.f;

    for (int c = 0; c < 4; c++) {
        asm volatile("cp.async.wait_group 0;" ::: "memory");
        __syncthreads();   // chunk c arrived; prior HID reads / LN2 writes done

        float acc1[2][4][4];
        #pragma unroll
        for (int a = 0; a < 2; a++)
            #pragma unroll
            for (int b = 0; b < 4; b++)
                #pragma unroll
                for (int q = 0; q < 4; q++) acc1[a][b][q] = 0.f;
        gemm64(A_B, WBUF, acc1, wm, wn, lrow, lhi);

        {
            float2 bs1[4];
            #pragma unroll
            for (int tn = 0; tn < 4; tn++)
                bs1[tn] = *(const float2*)(b1 + c * 128 + wn * 32 + tn * 8 + (lane & 3) * 2);
            #pragma unroll
            for (int tm = 0; tm < 2; tm++) {
                #pragma unroll
                for (int h = 0; h < 2; h++) {
                    const int row = wm * 32 + tm * 16 + (lane >> 2) + h * 8;
                    #pragma unroll
                    for (int tn = 0; tn < 4; tn++) {
                        const int nn = wn * 32 + tn * 8 + (lane & 3) * 2;
                        float v0 = gelu_fast(acc1[tm][tn][h * 2 + 0] + bs1[tn].x);
                        float v1 = gelu_fast(acc1[tm][tn][h * 2 + 1] + bs1[tn].y);
                        uint32_t boff = (uint32_t)((row << 7) + (nn & 63) * 2);
                        boff ^= (boff >> 3) & 0x70;
                        uint32_t dst = HID + ((nn >= 64) ? 8192u : 0u) + boff;
                        asm volatile("st.shared.b32 [%0], %1;" :: "r"(dst), "r"(packbf(v0, v1)) : "memory");
                    }
                }
            }
        }
        __syncthreads();   // HID visible

        gemm64(HID, WBUF + 32768u, acc2, wm, wn, lrow, lhi);
        __syncthreads();   // WBUF + HID reads done

        if (c < 3) mlp_stage_w(WBUF, W1, W2, c + 1, tid);
    }

    // ---- epilogue: out = acc2 + b2 + x1(regs), scattered ----
    float2 bs[4];
    #pragma unroll
    for (int tn = 0; tn < 4; tn++)
        bs[tn] = *(const float2*)(b2 + wn * 32 + tn * 8 + (lane & 3) * 2);
    #pragma unroll
    for (int tm = 0; tm < 2; tm++) {
        #pragma unroll
        for (int h8 = 0; h8 < 2; h8++) {
            const int m = m0 + wm * 32 + tm * 16 + (lane >> 2) + h8 * 8;
            int w = m >> 6, nt2 = m & 63;
            int b = w >> 8, wrem = w & 255;
            int wwi = wrem >> 4, wwj = wrem & 15;
            int yf = (wwi * 8 + (nt2 >> 3) + 4) & 127;
            int xf = (wwj * 8 + (nt2 & 7) + 4) & 127;
            size_t mo = ((size_t)b << 14) + (size_t)yf * 128 + xf;
            #pragma unroll
            for (int tn = 0; tn < 4; tn++) {
                const int nn = wn * 32 + tn * 8 + (lane & 3) * 2;
                float v0 = acc2[tm][tn][h8 * 2 + 0] + bs[tn].x + xv[tm][tn][h8 * 2 + 0];
                float v1 = acc2[tm][tn][h8 * 2 + 1] + bs[tn].y + xv[tm][tn][h8 * 2 + 1];
                *(float2*)(out + mo * 128 + nn) = make_float2(v0, v1);
            }
        }
    }
}

// ---------------- launch ----------------
extern "C" void kernel_launch(void* const* d_in, const int* in_sizes, int n_in,
                              void* d_out, int out_size)
{
    const float* x      = (const float*)d_in[0];
    const float* rpb    = (const float*)d_in[1];
    const float* n1g    = (const float*)d_in[2];
    const float* n1b    = (const float*)d_in[3];
    const float* qkv_w  = (const float*)d_in[4];
    const float* qkv_b  = (const float*)d_in[5];
    const float* proj_w = (const float*)d_in[6];
    const float* proj_b = (const float*)d_in[7];
    const float* n2g    = (const float*)d_in[8];
    const float* n2b    = (const float*)d_in[9];
    const float* fc1_w  = (const float*)d_in[10];
    const float* fc1_b  = (const float*)d_in[11];
    const float* fc2_w  = (const float*)d_in[12];
    const float* fc2_b  = (const float*)d_in[13];
    float* out = (float*)d_out;

    unsigned short *wq, *wp, *w1, *w2;
    cudaGetSymbolAddress((void**)&wq,  g_wq);
    cudaGetSymbolAddress((void**)&wp,  g_wp);
    cudaGetSymbolAddress((void**)&w1,  g_w1);
    cudaGetSymbolAddress((void**)&w2,  g_w2);

    cudaFuncSetAttribute(swin_fused, cudaFuncAttributeMaxDynamicSharedMemorySize, FSMEM);

    f2bf_all<<<192, 256>>>(qkv_w, wq, proj_w, wp, fc1_w, w1, fc2_w, w2);

    swin_fused<<<MTOK / 64, 256, FSMEM>>>(x, n1g, n1b, wq, qkv_b, wp, proj_b, rpb,
                                          n2g, n2b, w1, fc1_b, w2, fc2_b, out);
}